// round 1
// baseline (speedup 1.0000x reference)
#include <cuda_runtime.h>
#include <math.h>

// Problem constants
#define Bz 64
#define Lz 512
#define Iz 256
#define Hz 512
#define Gz 2048           // 4*H
#define Mz (Lz*Bz)        // 32768
#define NCD 64            // CTAs per direction in the recurrence kernel

// ---------------- scratch (device globals: allocation-free) ----------------
__device__ float g_xg[(size_t)2 * Mz * Gz];          // per-dir precomputed input gates (reused per layer)
__device__ float g_h0out[(size_t)Lz * Bz * 2 * Hz];  // layer-0 output [t][b][2H]
__device__ float g_hbuf[2 * Bz * Hz];                // running h per direction
__device__ unsigned g_cnt[2];                        // barrier arrival counters (return to 0)
__device__ unsigned g_gen[2];                        // barrier generation (monotonic; base-relative use)

// ============================================================================
// Kernel 1: input-projection GEMM + bias.
// Xg[dir][m][n] = bias[n] + sum_k A[m][k] * W[dir][n][k]
//   m = t*B + b.  layer0: A = x [b][t][k] (K=256).  layer1: A = g_h0out [m][k] (K=1024).
// Tiling: BM=128, BN=64, BK=16, 256 threads, 8x4 per-thread microtile.
// ============================================================================
#define GBM 128
#define GBN 64
#define GBK 16

__global__ void __launch_bounds__(256) gates_gemm(
    const float* __restrict__ x,
    const float* __restrict__ W_f, const float* __restrict__ bi_f, const float* __restrict__ bh_f,
    const float* __restrict__ W_r, const float* __restrict__ bi_r, const float* __restrict__ bh_r,
    int layer)
{
    const int dir = blockIdx.z;
    const float* __restrict__ W  = dir ? W_r  : W_f;
    const float* __restrict__ ba = dir ? bi_r : bi_f;
    const float* __restrict__ bb = dir ? bh_r : bh_f;
    const float* __restrict__ A  = layer ? (const float*)g_h0out : x;
    const int K  = layer ? (2*Hz) : Iz;
    const int sB = layer ? (2*Hz) : (Lz*Iz);   // stride for b = m%64
    const int sT = layer ? (Bz*2*Hz) : Iz;     // stride for t = m/64

    __shared__ float sA[GBK][GBM + 4];  // row = 132 floats = 528B (16B multiple)
    __shared__ float sB_[GBK][GBN + 4]; // row = 68 floats  = 272B (16B multiple)

    const int tid = threadIdx.x;
    const int tx = tid & 15;   // n group: 4 cols
    const int ty = tid >> 4;   // m group: 8 rows
    const int n0 = blockIdx.x * GBN;
    const int m0 = blockIdx.y * GBM;

    float bias[4];
#pragma unroll
    for (int j = 0; j < 4; j++) { const int n = n0 + tx*4 + j; bias[j] = ba[n] + bb[n]; }

    float acc[8][4];
#pragma unroll
    for (int i = 0; i < 8; i++)
#pragma unroll
        for (int j = 0; j < 4; j++) acc[i][j] = bias[j];

    const int arow = tid >> 2;   // 0..63
    const int aq   = tid & 3;    // float4 index within the 16-wide k slab

    for (int k0 = 0; k0 < K; k0 += GBK) {
        // Load A tile 128x16 (transposed into smem)
#pragma unroll
        for (int h2 = 0; h2 < 2; h2++) {
            const int row = arow + h2*64;
            const int mg = m0 + row;
            const float4 v = *((const float4*)(A + (size_t)(mg & 63)*sB + (size_t)(mg >> 6)*sT + k0 + aq*4));
            sA[aq*4+0][row] = v.x; sA[aq*4+1][row] = v.y;
            sA[aq*4+2][row] = v.z; sA[aq*4+3][row] = v.w;
        }
        // Load W tile 64x16 (transposed into smem)
        {
            const float4 v = *((const float4*)(W + (size_t)(n0 + arow)*K + k0 + aq*4));
            sB_[aq*4+0][arow] = v.x; sB_[aq*4+1][arow] = v.y;
            sB_[aq*4+2][arow] = v.z; sB_[aq*4+3][arow] = v.w;
        }
        __syncthreads();
#pragma unroll
        for (int kk = 0; kk < GBK; kk++) {
            const float4 a0 = *((const float4*)&sA[kk][ty*8]);
            const float4 a1 = *((const float4*)&sA[kk][ty*8 + 4]);
            const float4 b4 = *((const float4*)&sB_[kk][tx*4]);
            const float av[8] = {a0.x,a0.y,a0.z,a0.w,a1.x,a1.y,a1.z,a1.w};
            const float bv[4] = {b4.x,b4.y,b4.z,b4.w};
#pragma unroll
            for (int i = 0; i < 8; i++)
#pragma unroll
                for (int j = 0; j < 4; j++) acc[i][j] += av[i]*bv[j];
        }
        __syncthreads();
    }

    float* outp = g_xg + (size_t)dir * Mz * Gz;
#pragma unroll
    for (int i = 0; i < 8; i++) {
        const float4 v = make_float4(acc[i][0], acc[i][1], acc[i][2], acc[i][3]);
        *((float4*)(outp + (size_t)(m0 + ty*8 + i)*Gz + n0 + tx*4)) = v;
    }
}

// ============================================================================
// Kernel 2: persistent recurrence. 128 CTAs (64 per dir), 256 threads each.
// CTA `cb` owns h-columns [cb*8, cb*8+8) -> gate columns {g*512 + cb*8 + j}.
// Per step: gates(64x32) = Xg tile + h(64x512) @ WhhT(512x32); elementwise; h->L2; grid barrier.
// c stays in registers of the owning thread for all 512 steps.
// ============================================================================
__device__ __forceinline__ void grid_bar(int dir, unsigned target)
{
    __syncthreads();
    if (threadIdx.x == 0) {
        __threadfence();
        const unsigned prev = atomicAdd(&g_cnt[dir], 1u);
        if (prev == (unsigned)(NCD - 1)) {
            atomicExch(&g_cnt[dir], 0u);
            __threadfence();
            atomicExch(&g_gen[dir], target);
        } else {
            while (*((volatile unsigned*)&g_gen[dir]) != target) { }
        }
        __threadfence();
    }
    __syncthreads();
}

__global__ void __launch_bounds__(256) lstm_recur(
    const float* __restrict__ Whh_f, const float* __restrict__ Whh_r,
    float* __restrict__ dout, int layer)
{
    const int dir = (int)(blockIdx.x) / NCD;
    const int cb  = (int)(blockIdx.x) % NCD;
    const float* __restrict__ W  = dir ? Whh_r : Whh_f;
    const float* __restrict__ xg = g_xg + (size_t)dir * Mz * Gz;
    float* hb  = g_hbuf + dir * Bz * Hz;
    float* outp = layer ? dout : (float*)g_h0out;
    const int ts = layer ? (2*Hz) : (Bz*2*Hz);   // layer1: out[b][t][2H]; layer0: [t][b][2H]
    const int bs = layer ? (Lz*2*Hz) : (2*Hz);

    __shared__ float sH[64][68];   // h tile [b][k-chunk], row 272B (16B multiple)
    __shared__ float sW[64][34];   // Whh tile transposed [kk][col_local], row 136B (8B multiple)
    __shared__ float sG[64][34];   // gate exchange [b][col_local]
    __shared__ unsigned s_base;

    const int tid = threadIdx.x;
    const int c2  = tid & 15;      // owns cols {2c2, 2c2+1}
    const int bg  = tid >> 4;      // owns b rows {bg*4 .. bg*4+3}
    const int colA  = 2*c2;
    const int gcolA = (colA >> 3)*Hz + cb*8 + (colA & 7);  // gcolB = gcolA+1 (same gate block)

    if (tid == 0) s_base = *((volatile unsigned*)&g_gen[dir]);

    // zero-init owned h columns (re-done every launch & every graph replay)
#pragma unroll
    for (int r = 0; r < 2; r++) {
        const int id = tid + 256*r;
        hb[(id >> 3)*Hz + cb*8 + (id & 7)] = 0.f;
    }
    __syncthreads();
    const unsigned base = s_base;
    unsigned bar = 0;
    float creg[2] = {0.f, 0.f};
    grid_bar(dir, base + (++bar));   // h=0 visible everywhere

    for (int s = 0; s < Lz; s++) {
        const int t = dir ? (Lz - 1 - s) : s;

        float acc[4][2];
#pragma unroll
        for (int r = 0; r < 4; r++) {
            const int b = bg*4 + r;
            const float2 v = *((const float2*)(xg + ((size_t)t*Bz + b)*Gz + gcolA));
            acc[r][0] = v.x; acc[r][1] = v.y;
        }

        for (int kc = 0; kc < Hz; kc += 64) {
            // stage h tile (L2-coherent reads: other SMs wrote it last step)
#pragma unroll
            for (int r = 0; r < 4; r++) {
                const int b = (tid >> 4) + r*16;
                const float4 v = __ldcg((const float4*)(hb + b*Hz + kc + (tid & 15)*4));
                *((float4*)&sH[b][(tid & 15)*4]) = v;
            }
            // stage Whh tile (32 owned gate rows x 64 k), transposed
#pragma unroll
            for (int r2 = 0; r2 < 2; r2++) {
                const int idx = tid + 256*r2;
                const int wr = idx >> 4;           // 0..31 local gate col
                const int q  = idx & 15;
                const int gcol = (wr >> 3)*Hz + cb*8 + (wr & 7);
                const float4 v = *((const float4*)(W + (size_t)gcol*Hz + kc + q*4));
                sW[q*4+0][wr] = v.x; sW[q*4+1][wr] = v.y;
                sW[q*4+2][wr] = v.z; sW[q*4+3][wr] = v.w;
            }
            __syncthreads();
#pragma unroll
            for (int kk = 0; kk < 64; kk += 4) {
                float hv[4][4];
#pragma unroll
                for (int r = 0; r < 4; r++) {
                    const float4 v = *((const float4*)&sH[bg*4 + r][kk]);
                    hv[r][0]=v.x; hv[r][1]=v.y; hv[r][2]=v.z; hv[r][3]=v.w;
                }
#pragma unroll
                for (int u = 0; u < 4; u++) {
                    const float2 w2 = *((const float2*)&sW[kk + u][colA]);
#pragma unroll
                    for (int r = 0; r < 4; r++) {
                        acc[r][0] += hv[r][u]*w2.x;
                        acc[r][1] += hv[r][u]*w2.y;
                    }
                }
            }
            __syncthreads();
        }

        // exchange gates within CTA
#pragma unroll
        for (int r = 0; r < 4; r++) {
            sG[bg*4 + r][colA]     = acc[r][0];
            sG[bg*4 + r][colA + 1] = acc[r][1];
        }
        __syncthreads();

        // elementwise LSTM cell (each thread owns 2 (b, hcol) items; c in registers)
#pragma unroll
        for (int r = 0; r < 2; r++) {
            const int id = tid + 256*r;
            const int b = id >> 3, j = id & 7;
            const float iv = sG[b][j];
            const float fv = sG[b][8 + j];
            const float gv = sG[b][16 + j];
            const float ov = sG[b][24 + j];
            const float ig = 1.f/(1.f + expf(-iv));
            const float fg = 1.f/(1.f + expf(-fv));
            const float og = 1.f/(1.f + expf(-ov));
            const float c  = fg*creg[r] + ig*tanhf(gv);
            const float hv = og*tanhf(c);
            creg[r] = c;
            const int hcol = cb*8 + j;
            hb[b*Hz + hcol] = hv;
            outp[(size_t)t*ts + (size_t)b*bs + dir*Hz + hcol] = hv;
        }
        grid_bar(dir, base + (++bar));
    }
}

// ============================================================================
// Launch: gemm(L0) -> recur(L0) -> gemm(L1) -> recur(L1). Graph-capturable,
// allocation-free; all inter-kernel ordering via the capture stream.
// ============================================================================
extern "C" void kernel_launch(void* const* d_in, const int* in_sizes, int n_in,
                              void* d_out, int out_size)
{
    const float* x      = (const float*)d_in[0];
    const float* Wih_f0 = (const float*)d_in[1];
    const float* Whh_f0 = (const float*)d_in[2];
    const float* bih_f0 = (const float*)d_in[3];
    const float* bhh_f0 = (const float*)d_in[4];
    const float* Wih_r0 = (const float*)d_in[5];
    const float* Whh_r0 = (const float*)d_in[6];
    const float* bih_r0 = (const float*)d_in[7];
    const float* bhh_r0 = (const float*)d_in[8];
    const float* Wih_f1 = (const float*)d_in[9];
    const float* Whh_f1 = (const float*)d_in[10];
    const float* bih_f1 = (const float*)d_in[11];
    const float* bhh_f1 = (const float*)d_in[12];
    const float* Wih_r1 = (const float*)d_in[13];
    const float* Whh_r1 = (const float*)d_in[14];
    const float* bih_r1 = (const float*)d_in[15];
    const float* bhh_r1 = (const float*)d_in[16];
    float* outp = (float*)d_out;

    const dim3 gp(Gz/GBN, Mz/GBM, 2);   // (32, 256, 2)

    gates_gemm<<<gp, 256>>>(x, Wih_f0, bih_f0, bhh_f0, Wih_r0, bih_r0, bhh_r0, 0);
    lstm_recur<<<2*NCD, 256>>>(Whh_f0, Whh_r0, outp, 0);
    gates_gemm<<<gp, 256>>>(x, Wih_f1, bih_f1, bhh_f1, Wih_r1, bih_r1, bhh_r1, 1);
    lstm_recur<<<2*NCD, 256>>>(Whh_f1, Whh_r1, outp, 1);
}

// round 3
// speedup vs baseline: 1.2230x; 1.2230x over previous
#include <cuda_runtime.h>
#include <cuda_bf16.h>
#include <math.h>
#include <stdint.h>

// Problem constants
#define Bz 64
#define Lz 512
#define Iz 256
#define Hz 512
#define Gz 2048           // 4*H
#define Mz (Lz*Bz)        // 32768
#define NCD 64            // CTAs per direction in the recurrence kernel

// ---------------- scratch (device globals: allocation-free) ----------------
__device__ float g_xg[(size_t)2 * Mz * Gz];          // per-dir precomputed input gates (fp32)
__device__ float g_h0out[(size_t)Lz * Bz * 2 * Hz];  // layer-0 output [t][b][2H]
__device__ float g_hbuf[2 * Bz * Hz];                // running h per direction
__device__ unsigned g_cnt[2];                        // barrier arrival counters
__device__ unsigned g_gen[2];                        // barrier generation
__device__ __nv_bfloat16 g_Ahi[(size_t)Mz * 1024];   // split-bf16 activations (hi)
__device__ __nv_bfloat16 g_Alo[(size_t)Mz * 1024];   // split-bf16 activations (lo)
__device__ __nv_bfloat16 g_Whi[(size_t)2 * Gz * 1024];
__device__ __nv_bfloat16 g_Wlo[(size_t)2 * Gz * 1024];

// ======================= PTX helpers (base-ISA only) =======================
__device__ __forceinline__ uint32_t smem_to_u32(const void* p) {
    uint32_t a;
    asm("{ .reg .u64 t; cvta.to.shared.u64 t, %1; cvt.u32.u64 %0, t; }" : "=r"(a) : "l"(p));
    return a;
}
__device__ __forceinline__ void cpa16(uint32_t s, const void* g) {
    asm volatile("cp.async.cg.shared.global [%0], [%1], 16;" :: "r"(s), "l"(g));
}
__device__ __forceinline__ void ldsm_x4(uint32_t& r0, uint32_t& r1, uint32_t& r2, uint32_t& r3,
                                        uint32_t a) {
    asm volatile("ldmatrix.sync.aligned.m8n8.x4.shared.b16 {%0,%1,%2,%3}, [%4];"
                 : "=r"(r0), "=r"(r1), "=r"(r2), "=r"(r3) : "r"(a));
}
__device__ __forceinline__ void mma16816(float* d, const uint32_t* a, const uint32_t* b) {
    asm volatile("mma.sync.aligned.m16n8k16.row.col.f32.bf16.bf16.f32 "
                 "{%0,%1,%2,%3}, {%4,%5,%6,%7}, {%8,%9}, {%0,%1,%2,%3};"
                 : "+f"(d[0]), "+f"(d[1]), "+f"(d[2]), "+f"(d[3])
                 : "r"(a[0]), "r"(a[1]), "r"(a[2]), "r"(a[3]), "r"(b[0]), "r"(b[1]));
}

// ============================================================================
// Split-precision conversion kernels: fp32 -> (bf16 hi, bf16 lo)
// ============================================================================
__global__ void conv_split_A(const float* __restrict__ src, int layer, int kshift)
{
    const size_t i = ((size_t)blockIdx.x * 256 + threadIdx.x) * 4;
    const int K = 1 << kshift;
    const size_t m = i >> kshift;
    const size_t k = i & (size_t)(K - 1);
    float4 v;
    if (layer) v = *((const float4*)(g_h0out + (m << kshift) + k));
    else       v = *((const float4*)(src + ((m & 63) * 512 + (m >> 6)) * (size_t)K + k));

    __nv_bfloat16 hx = __float2bfloat16_rn(v.x), hy = __float2bfloat16_rn(v.y);
    __nv_bfloat16 hz = __float2bfloat16_rn(v.z), hw = __float2bfloat16_rn(v.w);
    __nv_bfloat16 lx = __float2bfloat16_rn(v.x - __bfloat162float(hx));
    __nv_bfloat16 ly = __float2bfloat16_rn(v.y - __bfloat162float(hy));
    __nv_bfloat16 lz = __float2bfloat16_rn(v.z - __bfloat162float(hz));
    __nv_bfloat16 lw = __float2bfloat16_rn(v.w - __bfloat162float(hw));
    *((__nv_bfloat162*)(g_Ahi + i))     = __halves2bfloat162(hx, hy);
    *((__nv_bfloat162*)(g_Ahi + i + 2)) = __halves2bfloat162(hz, hw);
    *((__nv_bfloat162*)(g_Alo + i))     = __halves2bfloat162(lx, ly);
    *((__nv_bfloat162*)(g_Alo + i + 2)) = __halves2bfloat162(lz, lw);
}

__global__ void conv_split_W(const float* __restrict__ Wf, const float* __restrict__ Wr, int K)
{
    const int dir = blockIdx.y;
    const size_t i = ((size_t)blockIdx.x * 256 + threadIdx.x) * 4;   // over 2048*K
    const float* src = dir ? Wr : Wf;
    const size_t off = (size_t)dir * Gz * K;
    const float4 v = *((const float4*)(src + i));
    __nv_bfloat16 hx = __float2bfloat16_rn(v.x), hy = __float2bfloat16_rn(v.y);
    __nv_bfloat16 hz = __float2bfloat16_rn(v.z), hw = __float2bfloat16_rn(v.w);
    __nv_bfloat16 lx = __float2bfloat16_rn(v.x - __bfloat162float(hx));
    __nv_bfloat16 ly = __float2bfloat16_rn(v.y - __bfloat162float(hy));
    __nv_bfloat16 lz = __float2bfloat16_rn(v.z - __bfloat162float(hz));
    __nv_bfloat16 lw = __float2bfloat16_rn(v.w - __bfloat162float(hw));
    *((__nv_bfloat162*)(g_Whi + off + i))     = __halves2bfloat162(hx, hy);
    *((__nv_bfloat162*)(g_Whi + off + i + 2)) = __halves2bfloat162(hz, hw);
    *((__nv_bfloat162*)(g_Wlo + off + i))     = __halves2bfloat162(lx, ly);
    *((__nv_bfloat162*)(g_Wlo + off + i + 2)) = __halves2bfloat162(lz, lw);
}

// ============================================================================
// mma.sync GEMM: Xg[dir][m][n] = bias[n] + sum_k A[m][k]*W[dir][n][k]
// Split-bf16: D += Ah*Wh + Ah*Wl + Al*Wh (fp32 accum in registers).
// CTA 128x128, BK=32, 8 warps (2Mx4N, warp tile 64x32), cp.async double-buffer.
// smem rows padded to 80B -> conflict-free ldmatrix.
// ============================================================================
#define TAH 0
#define TAL 10240
#define TBH 20480
#define TBL 30720
#define BUFB 40960
#define GEMM_SMEM (2*BUFB)

__global__ void __launch_bounds__(256) gates_gemm_mma(
    const float* __restrict__ bi_f, const float* __restrict__ bh_f,
    const float* __restrict__ bi_r, const float* __restrict__ bh_r, int K)
{
    extern __shared__ char smem[];
    const uint32_t sb = smem_to_u32(smem);
    __shared__ float sBias[128];

    const int tid = threadIdx.x;
    const int wid = tid >> 5;
    const int lane = tid & 31;
    const int warpM = wid >> 2;       // 0..1
    const int warpN = wid & 3;        // 0..3
    const int dir = blockIdx.z;
    const int n0 = blockIdx.x * 128;
    const int m0 = blockIdx.y * 128;

    const __nv_bfloat16* __restrict__ Wh = g_Whi + (size_t)dir * Gz * K;
    const __nv_bfloat16* __restrict__ Wl = g_Wlo + (size_t)dir * Gz * K;
    const float* bi = dir ? bi_r : bi_f;
    const float* bh = dir ? bh_r : bh_f;
    if (tid < 128) sBias[tid] = bi[n0 + tid] + bh[n0 + tid];

    float acc[4][4][4];
#pragma unroll
    for (int mt = 0; mt < 4; mt++)
#pragma unroll
        for (int nt = 0; nt < 4; nt++)
#pragma unroll
            for (int q = 0; q < 4; q++) acc[mt][nt][q] = 0.f;

    const int lrow = tid >> 2;        // 0..63  (idx mapping for loads)
    const int lseg = tid & 3;

    // ---- load helper (macro to keep addresses in registers) ----
#define LOAD_CHUNK(kc, boff) do { \
    _Pragma("unroll") \
    for (int i = 0; i < 2; i++) { \
        const int row = lrow + 64 * i; \
        const uint32_t so = (uint32_t)(row * 80 + lseg * 16); \
        const size_t ga = (size_t)(m0 + row) * K + (kc) + lseg * 8; \
        const size_t gb = (size_t)(n0 + row) * K + (kc) + lseg * 8; \
        cpa16(sb + (boff) + TAH + so, g_Ahi + ga); \
        cpa16(sb + (boff) + TAL + so, g_Alo + ga); \
        cpa16(sb + (boff) + TBH + so, Wh + gb); \
        cpa16(sb + (boff) + TBL + so, Wl + gb); \
    } \
    asm volatile("cp.async.commit_group;" ::: "memory"); \
} while (0)

    const int nch = K >> 5;
    LOAD_CHUNK(0, 0);

    // ldmatrix lane address components (fixed per thread)
    const int aRowOff = (lane & 7) + ((lane >> 3) & 1) * 8;   // within 16-row tile
    const int aColOff = ((lane >> 4) & 1) * 16;               // byte offset (8 elems)
    const int bRowOff = (lane & 7) + ((lane >> 4) & 1) * 8;
    const int bColOff = ((lane >> 3) & 1) * 16;

    for (int ch = 0; ch < nch; ch++) {
        if (ch + 1 < nch) {
            LOAD_CHUNK((ch + 1) << 5, (uint32_t)(((ch + 1) & 1) * BUFB));
            asm volatile("cp.async.wait_group 1;" ::: "memory");
        } else {
            asm volatile("cp.async.wait_group 0;" ::: "memory");
        }
        __syncthreads();

        const uint32_t boff = sb + (uint32_t)((ch & 1) * BUFB);
#pragma unroll
        for (int ks = 0; ks < 2; ks++) {
            const int kb = ks * 32;   // byte offset of this k16 within the 64B row
            uint32_t aH[4][4], aL[4][4], bH[4][2], bL[4][2];
#pragma unroll
            for (int mt = 0; mt < 4; mt++) {
                const uint32_t ra = (uint32_t)((warpM * 64 + mt * 16 + aRowOff) * 80 + kb + aColOff);
                ldsm_x4(aH[mt][0], aH[mt][1], aH[mt][2], aH[mt][3], boff + TAH + ra);
                ldsm_x4(aL[mt][0], aL[mt][1], aL[mt][2], aL[mt][3], boff + TAL + ra);
            }
#pragma unroll
            for (int p = 0; p < 2; p++) {
                const uint32_t rb = (uint32_t)((warpN * 32 + p * 16 + bRowOff) * 80 + kb + bColOff);
                uint32_t r0, r1, r2, r3;
                ldsm_x4(r0, r1, r2, r3, boff + TBH + rb);
                bH[2*p][0] = r0; bH[2*p][1] = r1; bH[2*p+1][0] = r2; bH[2*p+1][1] = r3;
                ldsm_x4(r0, r1, r2, r3, boff + TBL + rb);
                bL[2*p][0] = r0; bL[2*p][1] = r1; bL[2*p+1][0] = r2; bL[2*p+1][1] = r3;
            }
#pragma unroll
            for (int mt = 0; mt < 4; mt++)
#pragma unroll
                for (int nt = 0; nt < 4; nt++) {
                    mma16816(acc[mt][nt], aH[mt], bH[nt]);
                    mma16816(acc[mt][nt], aH[mt], bL[nt]);
                    mma16816(acc[mt][nt], aL[mt], bH[nt]);
                }
        }
        __syncthreads();
    }

    // epilogue: acc + bias -> g_xg (fp32)
    float* __restrict__ outp = g_xg + (size_t)dir * Mz * Gz;
    const int g  = lane >> 2;
    const int tg = lane & 3;
#pragma unroll
    for (int mt = 0; mt < 4; mt++) {
        const int m = m0 + warpM * 64 + mt * 16 + g;
#pragma unroll
        for (int nt = 0; nt < 4; nt++) {
            const int nl = warpN * 32 + nt * 8 + tg * 2;
            const float b0 = sBias[nl], b1 = sBias[nl + 1];
            float2 v0 = make_float2(acc[mt][nt][0] + b0, acc[mt][nt][1] + b1);
            float2 v1 = make_float2(acc[mt][nt][2] + b0, acc[mt][nt][3] + b1);
            *((float2*)(outp + (size_t)m * Gz + n0 + nl)) = v0;
            *((float2*)(outp + (size_t)(m + 8) * Gz + n0 + nl)) = v1;
        }
    }
#undef LOAD_CHUNK
}

// ============================================================================
// Persistent recurrence (fp32). Whh slice SMEM-resident (loaded once).
// 128 CTAs (64/dir), 256 threads. CTA cb owns h-cols [cb*8, cb*8+8).
// ============================================================================
__device__ __forceinline__ void grid_bar(int dir, unsigned target)
{
    __syncthreads();
    if (threadIdx.x == 0) {
        __threadfence();
        const unsigned prev = atomicAdd(&g_cnt[dir], 1u);
        if (prev == (unsigned)(NCD - 1)) {
            atomicExch(&g_cnt[dir], 0u);
            __threadfence();
            atomicExch(&g_gen[dir], target);
        } else {
            while (*((volatile unsigned*)&g_gen[dir]) != target) { }
        }
        __threadfence();
    }
    __syncthreads();
}

#define REC_SMEM ((512*36 + 64*68 + 64*34) * 4)   // 99840 bytes

__global__ void __launch_bounds__(256) lstm_recur(
    const float* __restrict__ Whh_f, const float* __restrict__ Whh_r,
    float* __restrict__ dout, int layer)
{
    const int dir = (int)(blockIdx.x) / NCD;
    const int cb  = (int)(blockIdx.x) % NCD;
    const float* __restrict__ W  = dir ? Whh_r : Whh_f;
    const float* __restrict__ xg = g_xg + (size_t)dir * Mz * Gz;
    float* hb   = g_hbuf + dir * Bz * Hz;
    float* outp = layer ? dout : (float*)g_h0out;
    const int ts = layer ? (2*Hz) : (Bz*2*Hz);
    const int bs = layer ? (Lz*2*Hz) : (2*Hz);

    extern __shared__ float dsm[];
    float (*sW)[36] = (float(*)[36])dsm;                       // [512][36]
    float (*sH)[68] = (float(*)[68])(dsm + 512*36);            // [64][68]
    float (*sG)[34] = (float(*)[34])(dsm + 512*36 + 64*68);    // [64][34]
    __shared__ unsigned s_base;

    const int tid = threadIdx.x;
    const int c2  = tid & 15;
    const int bg  = tid >> 4;
    const int colA  = 2*c2;
    const int gcolA = (colA >> 3)*Hz + cb*8 + (colA & 7);

    if (tid == 0) s_base = *((volatile unsigned*)&g_gen[dir]);

    // resident Whh slice: 32 owned gate cols x 512 k, transposed [k][col]
#pragma unroll
    for (int i = 0; i < 16; i++) {
        const int idx = tid + 256*i;       // 0..4095
        const int wr = idx >> 7;           // 0..31
        const int k4 = idx & 127;
        const int gcol = (wr >> 3)*Hz + cb*8 + (wr & 7);
        const float4 v = *((const float4*)(W + (size_t)gcol*Hz + k4*4));
        sW[k4*4+0][wr] = v.x; sW[k4*4+1][wr] = v.y;
        sW[k4*4+2][wr] = v.z; sW[k4*4+3][wr] = v.w;
    }

    // zero-init owned h columns
#pragma unroll
    for (int r = 0; r < 2; r++) {
        const int id = tid + 256*r;
        hb[(id >> 3)*Hz + cb*8 + (id & 7)] = 0.f;
    }
    __syncthreads();
    const unsigned base = s_base;
    unsigned bar = 0;
    float creg[2] = {0.f, 0.f};
    grid_bar(dir, base + (++bar));

    for (int s = 0; s < Lz; s++) {
        const int t = dir ? (Lz - 1 - s) : s;

        float acc[4][2];
#pragma unroll
        for (int r = 0; r < 4; r++) {
            const int b = bg*4 + r;
            const float2 v = *((const float2*)(xg + ((size_t)t*Bz + b)*Gz + gcolA));
            acc[r][0] = v.x; acc[r][1] = v.y;
        }

        for (int kc = 0; kc < Hz; kc += 64) {
            // stage h tile from L2
#pragma unroll
            for (int r = 0; r < 4; r++) {
                const int b = (tid >> 4) + r*16;
                const float4 v = __ldcg((const float4*)(hb + b*Hz + kc + (tid & 15)*4));
                *((float4*)&sH[b][(tid & 15)*4]) = v;
            }
            __syncthreads();
#pragma unroll
            for (int kk = 0; kk < 64; kk += 4) {
                float hv[4][4];
#pragma unroll
                for (int r = 0; r < 4; r++) {
                    const float4 v = *((const float4*)&sH[bg*4 + r][kk]);
                    hv[r][0]=v.x; hv[r][1]=v.y; hv[r][2]=v.z; hv[r][3]=v.w;
                }
#pragma unroll
                for (int u = 0; u < 4; u++) {
                    const float2 w2 = *((const float2*)&sW[kc + kk + u][colA]);
#pragma unroll
                    for (int r = 0; r < 4; r++) {
                        acc[r][0] += hv[r][u]*w2.x;
                        acc[r][1] += hv[r][u]*w2.y;
                    }
                }
            }
            __syncthreads();
        }

        // exchange gates within CTA
#pragma unroll
        for (int r = 0; r < 4; r++) {
            sG[bg*4 + r][colA]     = acc[r][0];
            sG[bg*4 + r][colA + 1] = acc[r][1];
        }
        __syncthreads();

        // elementwise LSTM cell
#pragma unroll
        for (int r = 0; r < 2; r++) {
            const int id = tid + 256*r;
            const int b = id >> 3, j = id & 7;
            const float iv = sG[b][j];
            const float fv = sG[b][8 + j];
            const float gv = sG[b][16 + j];
            const float ov = sG[b][24 + j];
            const float ig = 1.f/(1.f + expf(-iv));
            const float fg = 1.f/(1.f + expf(-fv));
            const float og = 1.f/(1.f + expf(-ov));
            const float c  = fg*creg[r] + ig*tanhf(gv);
            const float hv = og*tanhf(c);
            creg[r] = c;
            const int hcol = cb*8 + j;
            hb[b*Hz + hcol] = hv;
            outp[(size_t)t*ts + (size_t)b*bs + dir*Hz + hcol] = hv;
        }
        grid_bar(dir, base + (++bar));
    }
}

// ============================================================================
// Launch sequence (graph-capturable, allocation-free)
// ============================================================================
extern "C" void kernel_launch(void* const* d_in, const int* in_sizes, int n_in,
                              void* d_out, int out_size)
{
    const float* x      = (const float*)d_in[0];
    const float* Wih_f0 = (const float*)d_in[1];
    const float* Whh_f0 = (const float*)d_in[2];
    const float* bih_f0 = (const float*)d_in[3];
    const float* bhh_f0 = (const float*)d_in[4];
    const float* Wih_r0 = (const float*)d_in[5];
    const float* Whh_r0 = (const float*)d_in[6];
    const float* bih_r0 = (const float*)d_in[7];
    const float* bhh_r0 = (const float*)d_in[8];
    const float* Wih_f1 = (const float*)d_in[9];
    const float* Whh_f1 = (const float*)d_in[10];
    const float* bih_f1 = (const float*)d_in[11];
    const float* bhh_f1 = (const float*)d_in[12];
    const float* Wih_r1 = (const float*)d_in[13];
    const float* Whh_r1 = (const float*)d_in[14];
    const float* bih_r1 = (const float*)d_in[15];
    const float* bhh_r1 = (const float*)d_in[16];
    float* outp = (float*)d_out;

    cudaFuncSetAttribute(gates_gemm_mma, cudaFuncAttributeMaxDynamicSharedMemorySize, GEMM_SMEM);
    cudaFuncSetAttribute(lstm_recur,     cudaFuncAttributeMaxDynamicSharedMemorySize, REC_SMEM);

    const dim3 gemm_grid(Gz/128, Mz/128, 2);     // (16, 256, 2)

    // ---- layer 0 (K = 256) ----
    conv_split_W<<<dim3((Gz*256)/1024, 2), 256>>>(Wih_f0, Wih_r0, 256);
    conv_split_A<<<(Mz*256)/1024, 256>>>(x, 0, 8);
    gates_gemm_mma<<<gemm_grid, 256, GEMM_SMEM>>>(bih_f0, bhh_f0, bih_r0, bhh_r0, 256);
    lstm_recur<<<2*NCD, 256, REC_SMEM>>>(Whh_f0, Whh_r0, outp, 0);

    // ---- layer 1 (K = 1024) ----
    conv_split_W<<<dim3((Gz*1024)/1024, 2), 256>>>(Wih_f1, Wih_r1, 1024);
    conv_split_A<<<(Mz*1024)/1024, 256>>>(x, 1, 10);
    gates_gemm_mma<<<gemm_grid, 256, GEMM_SMEM>>>(bih_f1, bhh_f1, bih_r1, bhh_r1, 1024);
    lstm_recur<<<2*NCD, 256, REC_SMEM>>>(Whh_f1, Whh_r1, outp, 1);
}

// round 4
// speedup vs baseline: 2.4072x; 1.9683x over previous
#include <cuda_runtime.h>
#include <cuda_bf16.h>
#include <cuda_fp16.h>
#include <math.h>
#include <stdint.h>

// Problem constants
#define Bz 64
#define Lz 512
#define Iz 256
#define Hz 512
#define Gz 2048           // 4*H
#define Mz (Lz*Bz)        // 32768
#define NCD 64            // CTAs per direction in the recurrence kernel

// ---------------- scratch (device globals: allocation-free) ----------------
__device__ float g_xg[(size_t)2 * Mz * Gz];          // per-dir precomputed input gates (fp32)
__device__ float g_h0out[(size_t)Lz * Bz * 2 * Hz];  // layer-0 output [t][b][2H]
__device__ __half g_hf[2 * Bz * Hz];                 // running h per direction (fp16)
__device__ unsigned g_cnt[2];                        // barrier arrival counters
__device__ unsigned g_gen[2];                        // barrier generation
__device__ __nv_bfloat16 g_Ahi[(size_t)Mz * 1024];   // split-bf16 activations (hi)
__device__ __nv_bfloat16 g_Alo[(size_t)Mz * 1024];   // split-bf16 activations (lo)
__device__ __nv_bfloat16 g_Whi[(size_t)2 * Gz * 1024];
__device__ __nv_bfloat16 g_Wlo[(size_t)2 * Gz * 1024];

// ======================= PTX helpers (base-ISA only) =======================
__device__ __forceinline__ uint32_t smem_to_u32(const void* p) {
    uint32_t a;
    asm("{ .reg .u64 t; cvta.to.shared.u64 t, %1; cvt.u32.u64 %0, t; }" : "=r"(a) : "l"(p));
    return a;
}
__device__ __forceinline__ void cpa16(uint32_t s, const void* g) {
    asm volatile("cp.async.cg.shared.global [%0], [%1], 16;" :: "r"(s), "l"(g));
}
__device__ __forceinline__ void ldsm_x4(uint32_t& r0, uint32_t& r1, uint32_t& r2, uint32_t& r3,
                                        uint32_t a) {
    asm volatile("ldmatrix.sync.aligned.m8n8.x4.shared.b16 {%0,%1,%2,%3}, [%4];"
                 : "=r"(r0), "=r"(r1), "=r"(r2), "=r"(r3) : "r"(a));
}
__device__ __forceinline__ void mma16816(float* d, const uint32_t* a, const uint32_t* b) {
    asm volatile("mma.sync.aligned.m16n8k16.row.col.f32.bf16.bf16.f32 "
                 "{%0,%1,%2,%3}, {%4,%5,%6,%7}, {%8,%9}, {%0,%1,%2,%3};"
                 : "+f"(d[0]), "+f"(d[1]), "+f"(d[2]), "+f"(d[3])
                 : "r"(a[0]), "r"(a[1]), "r"(a[2]), "r"(a[3]), "r"(b[0]), "r"(b[1]));
}
__device__ __forceinline__ void mma16816h(float* d, const uint32_t* a, const uint32_t* b) {
    asm volatile("mma.sync.aligned.m16n8k16.row.col.f32.f16.f16.f32 "
                 "{%0,%1,%2,%3}, {%4,%5,%6,%7}, {%8,%9}, {%0,%1,%2,%3};"
                 : "+f"(d[0]), "+f"(d[1]), "+f"(d[2]), "+f"(d[3])
                 : "r"(a[0]), "r"(a[1]), "r"(a[2]), "r"(a[3]), "r"(b[0]), "r"(b[1]));
}

// ============================================================================
// Split-precision conversion kernels: fp32 -> (bf16 hi, bf16 lo)
// ============================================================================
__global__ void conv_split_A(const float* __restrict__ src, int layer, int kshift)
{
    const size_t i = ((size_t)blockIdx.x * 256 + threadIdx.x) * 4;
    const int K = 1 << kshift;
    const size_t m = i >> kshift;
    const size_t k = i & (size_t)(K - 1);
    float4 v;
    if (layer) v = *((const float4*)(g_h0out + (m << kshift) + k));
    else       v = *((const float4*)(src + ((m & 63) * 512 + (m >> 6)) * (size_t)K + k));

    __nv_bfloat16 hx = __float2bfloat16_rn(v.x), hy = __float2bfloat16_rn(v.y);
    __nv_bfloat16 hz = __float2bfloat16_rn(v.z), hw = __float2bfloat16_rn(v.w);
    __nv_bfloat16 lx = __float2bfloat16_rn(v.x - __bfloat162float(hx));
    __nv_bfloat16 ly = __float2bfloat16_rn(v.y - __bfloat162float(hy));
    __nv_bfloat16 lz = __float2bfloat16_rn(v.z - __bfloat162float(hz));
    __nv_bfloat16 lw = __float2bfloat16_rn(v.w - __bfloat162float(hw));
    *((__nv_bfloat162*)(g_Ahi + i))     = __halves2bfloat162(hx, hy);
    *((__nv_bfloat162*)(g_Ahi + i + 2)) = __halves2bfloat162(hz, hw);
    *((__nv_bfloat162*)(g_Alo + i))     = __halves2bfloat162(lx, ly);
    *((__nv_bfloat162*)(g_Alo + i + 2)) = __halves2bfloat162(lz, lw);
}

__global__ void conv_split_W(const float* __restrict__ Wf, const float* __restrict__ Wr, int K)
{
    const int dir = blockIdx.y;
    const size_t i = ((size_t)blockIdx.x * 256 + threadIdx.x) * 4;   // over 2048*K
    const float* src = dir ? Wr : Wf;
    const size_t off = (size_t)dir * Gz * K;
    const float4 v = *((const float4*)(src + i));
    __nv_bfloat16 hx = __float2bfloat16_rn(v.x), hy = __float2bfloat16_rn(v.y);
    __nv_bfloat16 hz = __float2bfloat16_rn(v.z), hw = __float2bfloat16_rn(v.w);
    __nv_bfloat16 lx = __float2bfloat16_rn(v.x - __bfloat162float(hx));
    __nv_bfloat16 ly = __float2bfloat16_rn(v.y - __bfloat162float(hy));
    __nv_bfloat16 lz = __float2bfloat16_rn(v.z - __bfloat162float(hz));
    __nv_bfloat16 lw = __float2bfloat16_rn(v.w - __bfloat162float(hw));
    *((__nv_bfloat162*)(g_Whi + off + i))     = __halves2bfloat162(hx, hy);
    *((__nv_bfloat162*)(g_Whi + off + i + 2)) = __halves2bfloat162(hz, hw);
    *((__nv_bfloat162*)(g_Wlo + off + i))     = __halves2bfloat162(lx, ly);
    *((__nv_bfloat162*)(g_Wlo + off + i + 2)) = __halves2bfloat162(lz, lw);
}

// ============================================================================
// mma.sync GEMM (unchanged from R3, proven): Xg = bias + A @ W^T, split-bf16.
// ============================================================================
#define TAH 0
#define TAL 10240
#define TBH 20480
#define TBL 30720
#define BUFB 40960
#define GEMM_SMEM (2*BUFB)

__global__ void __launch_bounds__(256) gates_gemm_mma(
    const float* __restrict__ bi_f, const float* __restrict__ bh_f,
    const float* __restrict__ bi_r, const float* __restrict__ bh_r, int K)
{
    extern __shared__ char smem[];
    const uint32_t sb = smem_to_u32(smem);
    __shared__ float sBias[128];

    const int tid = threadIdx.x;
    const int wid = tid >> 5;
    const int lane = tid & 31;
    const int warpM = wid >> 2;       // 0..1
    const int warpN = wid & 3;        // 0..3
    const int dir = blockIdx.z;
    const int n0 = blockIdx.x * 128;
    const int m0 = blockIdx.y * 128;

    const __nv_bfloat16* __restrict__ Wh = g_Whi + (size_t)dir * Gz * K;
    const __nv_bfloat16* __restrict__ Wl = g_Wlo + (size_t)dir * Gz * K;
    const float* bi = dir ? bi_r : bi_f;
    const float* bh = dir ? bh_r : bh_f;
    if (tid < 128) sBias[tid] = bi[n0 + tid] + bh[n0 + tid];

    float acc[4][4][4];
#pragma unroll
    for (int mt = 0; mt < 4; mt++)
#pragma unroll
        for (int nt = 0; nt < 4; nt++)
#pragma unroll
            for (int q = 0; q < 4; q++) acc[mt][nt][q] = 0.f;

    const int lrow = tid >> 2;
    const int lseg = tid & 3;

#define LOAD_CHUNK(kc, boff) do { \
    _Pragma("unroll") \
    for (int i = 0; i < 2; i++) { \
        const int row = lrow + 64 * i; \
        const uint32_t so = (uint32_t)(row * 80 + lseg * 16); \
        const size_t ga = (size_t)(m0 + row) * K + (kc) + lseg * 8; \
        const size_t gb = (size_t)(n0 + row) * K + (kc) + lseg * 8; \
        cpa16(sb + (boff) + TAH + so, g_Ahi + ga); \
        cpa16(sb + (boff) + TAL + so, g_Alo + ga); \
        cpa16(sb + (boff) + TBH + so, Wh + gb); \
        cpa16(sb + (boff) + TBL + so, Wl + gb); \
    } \
    asm volatile("cp.async.commit_group;" ::: "memory"); \
} while (0)

    const int nch = K >> 5;
    LOAD_CHUNK(0, 0);

    const int aRowOff = (lane & 7) + ((lane >> 3) & 1) * 8;
    const int aColOff = ((lane >> 4) & 1) * 16;
    const int bRowOff = (lane & 7) + ((lane >> 4) & 1) * 8;
    const int bColOff = ((lane >> 3) & 1) * 16;

    for (int ch = 0; ch < nch; ch++) {
        if (ch + 1 < nch) {
            LOAD_CHUNK((ch + 1) << 5, (uint32_t)(((ch + 1) & 1) * BUFB));
            asm volatile("cp.async.wait_group 1;" ::: "memory");
        } else {
            asm volatile("cp.async.wait_group 0;" ::: "memory");
        }
        __syncthreads();

        const uint32_t boff = sb + (uint32_t)((ch & 1) * BUFB);
#pragma unroll
        for (int ks = 0; ks < 2; ks++) {
            const int kb = ks * 32;
            uint32_t aH[4][4], aL[4][4], bH[4][2], bL[4][2];
#pragma unroll
            for (int mt = 0; mt < 4; mt++) {
                const uint32_t ra = (uint32_t)((warpM * 64 + mt * 16 + aRowOff) * 80 + kb + aColOff);
                ldsm_x4(aH[mt][0], aH[mt][1], aH[mt][2], aH[mt][3], boff + TAH + ra);
                ldsm_x4(aL[mt][0], aL[mt][1], aL[mt][2], aL[mt][3], boff + TAL + ra);
            }
#pragma unroll
            for (int p = 0; p < 2; p++) {
                const uint32_t rb = (uint32_t)((warpN * 32 + p * 16 + bRowOff) * 80 + kb + bColOff);
                uint32_t r0, r1, r2, r3;
                ldsm_x4(r0, r1, r2, r3, boff + TBH + rb);
                bH[2*p][0] = r0; bH[2*p][1] = r1; bH[2*p+1][0] = r2; bH[2*p+1][1] = r3;
                ldsm_x4(r0, r1, r2, r3, boff + TBL + rb);
                bL[2*p][0] = r0; bL[2*p][1] = r1; bL[2*p+1][0] = r2; bL[2*p+1][1] = r3;
            }
#pragma unroll
            for (int mt = 0; mt < 4; mt++)
#pragma unroll
                for (int nt = 0; nt < 4; nt++) {
                    mma16816(acc[mt][nt], aH[mt], bH[nt]);
                    mma16816(acc[mt][nt], aH[mt], bL[nt]);
                    mma16816(acc[mt][nt], aL[mt], bH[nt]);
                }
        }
        __syncthreads();
    }

    float* __restrict__ outp = g_xg + (size_t)dir * Mz * Gz;
    const int g  = lane >> 2;
    const int tg = lane & 3;
#pragma unroll
    for (int mt = 0; mt < 4; mt++) {
        const int m = m0 + warpM * 64 + mt * 16 + g;
#pragma unroll
        for (int nt = 0; nt < 4; nt++) {
            const int nl = warpN * 32 + nt * 8 + tg * 2;
            const float b0 = sBias[nl], b1 = sBias[nl + 1];
            float2 v0 = make_float2(acc[mt][nt][0] + b0, acc[mt][nt][1] + b1);
            float2 v1 = make_float2(acc[mt][nt][2] + b0, acc[mt][nt][3] + b1);
            *((float2*)(outp + (size_t)m * Gz + n0 + nl)) = v0;
            *((float2*)(outp + (size_t)(m + 8) * Gz + n0 + nl)) = v1;
        }
    }
#undef LOAD_CHUNK
}

// ============================================================================
// Persistent recurrence v2: tensor-core matvec.
// 128 CTAs (64/dir), 256 thr. CTA cb owns h-cols [cb*8,cb*8+8) -> 32 gate cols.
// h is fp16 (single); Whh slice fp16 hi+lo, SMEM-resident (converted in-kernel).
// Per step: cp.async h(64x512 fp16) + xg tile; 2-term HMMA (h*Whi + h*Wlo);
// elementwise in fp32; h -> fp16 global; grid barrier.
// ============================================================================
__device__ __forceinline__ void grid_bar(int dir, unsigned target)
{
    __syncthreads();
    if (threadIdx.x == 0) {
        __threadfence();
        const unsigned prev = atomicAdd(&g_cnt[dir], 1u);
        if (prev == (unsigned)(NCD - 1)) {
            atomicExch(&g_cnt[dir], 0u);
            __threadfence();
            atomicExch(&g_gen[dir], target);
        } else {
            while (*((volatile unsigned*)&g_gen[dir]) != target) { }
        }
        __threadfence();
    }
    __syncthreads();
}

// dynamic smem layout (bytes)
#define RP 1040                   // row pitch: 520 halfs (512 + 8 pad)
#define SWHI 0                    // [32][520] fp16   33280 B
#define SWLO 33280                // [32][520] fp16   33280 B
#define SAH  66560                // [64][520] fp16   66560 B
#define SXG  133120               // [64][36] fp32     9216 B
#define SGT  142336               // [64][34] fp32     8704 B
#define REC_SMEM 151040

__global__ void __launch_bounds__(256) lstm_recur_mma(
    const float* __restrict__ Whh_f, const float* __restrict__ Whh_r,
    float* __restrict__ dout, int layer)
{
    extern __shared__ char dsm[];
    const uint32_t sb = smem_to_u32(dsm);
    __shared__ unsigned s_base;

    const int dir = (int)(blockIdx.x) / NCD;
    const int cb  = (int)(blockIdx.x) % NCD;
    const float* __restrict__ W  = dir ? Whh_r : Whh_f;
    const float* __restrict__ xg = g_xg + (size_t)dir * Mz * Gz;
    __half* hb = g_hf + dir * Bz * Hz;
    float* outp = layer ? dout : (float*)g_h0out;
    const int ts = layer ? (2*Hz) : (Bz*2*Hz);
    const int bs = layer ? (Lz*2*Hz) : (2*Hz);

    const int tid = threadIdx.x;
    const int wid = tid >> 5;
    const int lane = tid & 31;
    const int warpM = wid & 3;        // 4 warps over M=64 (16 rows each)
    const int warpN = wid >> 2;       // 2 warps over N=32 (16 cols each)

    if (tid == 0) s_base = *((volatile unsigned*)&g_gen[dir]);

    // ---- stage Whh slice -> fp16 hi/lo in smem (one time) ----
    __half* sWhi = (__half*)(dsm + SWHI);
    __half* sWlo = (__half*)(dsm + SWLO);
#pragma unroll
    for (int i = 0; i < 16; i++) {
        const int idx = tid + 256 * i;       // 0..4095 over 32 rows x 128 float4
        const int n  = idx >> 7;             // local gate col 0..31
        const int f4 = idx & 127;
        const int gcol = (n >> 3) * Hz + cb * 8 + (n & 7);
        const float4 v = *((const float4*)(W + (size_t)gcol * Hz + f4 * 4));
        __half h0 = __float2half_rn(v.x), h1 = __float2half_rn(v.y);
        __half h2 = __float2half_rn(v.z), h3 = __float2half_rn(v.w);
        __half l0 = __float2half_rn(v.x - __half2float(h0));
        __half l1 = __float2half_rn(v.y - __half2float(h1));
        __half l2 = __float2half_rn(v.z - __half2float(h2));
        __half l3 = __float2half_rn(v.w - __half2float(h3));
        __half* ph = sWhi + n * 520 + f4 * 4;
        __half* pl = sWlo + n * 520 + f4 * 4;
        ph[0]=h0; ph[1]=h1; ph[2]=h2; ph[3]=h3;
        pl[0]=l0; pl[1]=l1; pl[2]=l2; pl[3]=l3;
    }

    // zero-init owned h columns (fp16)
#pragma unroll
    for (int r = 0; r < 2; r++) {
        const int id = tid + 256 * r;
        hb[(id >> 3) * Hz + cb * 8 + (id & 7)] = __float2half(0.f);
    }
    __syncthreads();
    const unsigned base = s_base;
    unsigned bar = 0;
    float creg[2] = {0.f, 0.f};
    grid_bar(dir, base + (++bar));   // h=0 + W staged visible

    const int aRowOff = (lane & 7) + ((lane >> 3) & 1) * 8;
    const int aColOff = ((lane >> 4) & 1) * 16;
    const int bRowOff = (lane & 7) + ((lane >> 4) & 1) * 8;
    const int bColOff = ((lane >> 3) & 1) * 16;

    float* sXGf = (float*)(dsm + SXG);   // [64][36]
    float* sGf  = (float*)(dsm + SGT);   // [64][34]

    for (int s = 0; s < Lz; s++) {
        const int t = dir ? (Lz - 1 - s) : s;

        // ---- cp.async h tile: 64 rows x 1024B ----
#pragma unroll
        for (int i = 0; i < 16; i++) {
            const int idx = tid + 256 * i;   // 0..4095
            const int b = idx >> 6, seg = idx & 63;
            cpa16(sb + SAH + b * RP + seg * 16, hb + b * Hz + seg * 8);
        }
        // ---- cp.async xg tile: [64][32] fp32, 4 groups of 8 ----
#pragma unroll
        for (int i = 0; i < 2; i++) {
            const int idx = tid + 256 * i;   // 0..511
            const int b = idx >> 3, rem = idx & 7;
            const int g = rem >> 1, q = rem & 1;
            cpa16(sb + SXG + b * 144 + g * 32 + q * 16,
                  xg + ((size_t)t * Bz + b) * Gz + g * Hz + cb * 8 + q * 4);
        }
        asm volatile("cp.async.commit_group;" ::: "memory");
        asm volatile("cp.async.wait_group 0;" ::: "memory");
        __syncthreads();

        // ---- MMA: gates(64x32) = h(64x512) @ Wslice^T, 2 terms (hi+lo) ----
        float acc0[4] = {0.f,0.f,0.f,0.f};
        float acc1[4] = {0.f,0.f,0.f,0.f};
        const uint32_t aBase = sb + SAH + (uint32_t)((warpM * 16 + aRowOff) * RP + aColOff);
        const uint32_t bhBase = sb + SWHI + (uint32_t)((warpN * 16 + bRowOff) * RP + bColOff);
        const uint32_t blBase = sb + SWLO + (uint32_t)((warpN * 16 + bRowOff) * RP + bColOff);
#pragma unroll 8
        for (int ks = 0; ks < 32; ks++) {
            uint32_t a[4], bh[4], bl[4];
            ldsm_x4(a[0], a[1], a[2], a[3], aBase + ks * 32);
            ldsm_x4(bh[0], bh[1], bh[2], bh[3], bhBase + ks * 32);
            ldsm_x4(bl[0], bl[1], bl[2], bl[3], blBase + ks * 32);
            mma16816h(acc0, a, bh);
            mma16816h(acc0, a, bl + 0);   // placeholder to keep symmetry (overwritten below)
            // NOTE: acc0 uses bh[0..1]/bl[0..1]; acc1 uses bh[2..3]/bl[2..3]
            mma16816h(acc1, a, bh + 2);
            mma16816h(acc1, a, bl + 2);
        }
        // fix: the second mma above fed bl[0..1] into acc0 — that IS the lo term
        // for n8-tile 0; tile-1 handled by the bh+2/bl+2 pair. (4 MMAs/kstep total.)

        // ---- write frags to sG ----
        {
            const int g = lane >> 2, tg = lane & 3;
            const int r = warpM * 16 + g;
            const int c = warpN * 16 + tg * 2;
            *((float2*)(sGf + r * 34 + c))           = make_float2(acc0[0], acc0[1]);
            *((float2*)(sGf + (r + 8) * 34 + c))     = make_float2(acc0[2], acc0[3]);
            *((float2*)(sGf + r * 34 + c + 8))       = make_float2(acc1[0], acc1[1]);
            *((float2*)(sGf + (r + 8) * 34 + c + 8)) = make_float2(acc1[2], acc1[3]);
        }
        __syncthreads();

        // ---- elementwise LSTM cell ----
#pragma unroll
        for (int r = 0; r < 2; r++) {
            const int id = tid + 256 * r;
            const int b = id >> 3, j = id & 7;
            const float iv = sGf[b*34 + j]      + sXGf[b*36 + j];
            const float fv = sGf[b*34 + 8 + j]  + sXGf[b*36 + 8 + j];
            const float gv = sGf[b*34 + 16 + j] + sXGf[b*36 + 16 + j];
            const float ov = sGf[b*34 + 24 + j] + sXGf[b*36 + 24 + j];
            const float ig = 1.f/(1.f + expf(-iv));
            const float fg = 1.f/(1.f + expf(-fv));
            const float og = 1.f/(1.f + expf(-ov));
            const float c  = fg*creg[r] + ig*tanhf(gv);
            const float hv = og*tanhf(c);
            creg[r] = c;
            const int hcol = cb*8 + j;
            hb[b*Hz + hcol] = __float2half(hv);
            outp[(size_t)t*ts + (size_t)b*bs + dir*Hz + hcol] = hv;
        }
        grid_bar(dir, base + (++bar));
    }
}

// ============================================================================
// Launch sequence (graph-capturable, allocation-free)
// ============================================================================
extern "C" void kernel_launch(void* const* d_in, const int* in_sizes, int n_in,
                              void* d_out, int out_size)
{
    const float* x      = (const float*)d_in[0];
    const float* Wih_f0 = (const float*)d_in[1];
    const float* Whh_f0 = (const float*)d_in[2];
    const float* bih_f0 = (const float*)d_in[3];
    const float* bhh_f0 = (const float*)d_in[4];
    const float* Wih_r0 = (const float*)d_in[5];
    const float* Whh_r0 = (const float*)d_in[6];
    const float* bih_r0 = (const float*)d_in[7];
    const float* bhh_r0 = (const float*)d_in[8];
    const float* Wih_f1 = (const float*)d_in[9];
    const float* Whh_f1 = (const float*)d_in[10];
    const float* bih_f1 = (const float*)d_in[11];
    const float* bhh_f1 = (const float*)d_in[12];
    const float* Wih_r1 = (const float*)d_in[13];
    const float* Whh_r1 = (const float*)d_in[14];
    const float* bih_r1 = (const float*)d_in[15];
    const float* bhh_r1 = (const float*)d_in[16];
    float* outp = (float*)d_out;

    cudaFuncSetAttribute(gates_gemm_mma, cudaFuncAttributeMaxDynamicSharedMemorySize, GEMM_SMEM);
    cudaFuncSetAttribute(lstm_recur_mma, cudaFuncAttributeMaxDynamicSharedMemorySize, REC_SMEM);

    const dim3 gemm_grid(Gz/128, Mz/128, 2);     // (16, 256, 2)

    // ---- layer 0 (K = 256) ----
    conv_split_W<<<dim3((Gz*256)/1024, 2), 256>>>(Wih_f0, Wih_r0, 256);
    conv_split_A<<<(Mz*256)/1024, 256>>>(x, 0, 8);
    gates_gemm_mma<<<gemm_grid, 256, GEMM_SMEM>>>(bih_f0, bhh_f0, bih_r0, bhh_r0, 256);
    lstm_recur_mma<<<2*NCD, 256, REC_SMEM>>>(Whh_f0, Whh_r0, outp, 0);

    // ---- layer 1 (K = 1024) ----
    conv_split_W<<<dim3((Gz*1024)/1024, 2), 256>>>(Wih_f1, Wih_r1, 1024);
    conv_split_A<<<(Mz*1024)/1024, 256>>>(x, 1, 10);
    gates_gemm_mma<<<gemm_grid, 256, GEMM_SMEM>>>(bih_f1, bhh_f1, bih_r1, bhh_r1, 1024);
    lstm_recur_mma<<<2*NCD, 256, REC_SMEM>>>(Whh_f1, Whh_r1, outp, 1);
}

// round 5
// speedup vs baseline: 3.2068x; 1.3322x over previous
#include <cuda_runtime.h>
#include <cuda_fp16.h>
#include <math.h>
#include <stdint.h>

// Problem constants
#define Bz 64
#define Lz 512
#define Iz 256
#define Hz 512
#define Gz 2048           // 4*H
#define Mz (Lz*Bz)        // 32768
#define NCD 64            // CTAs per direction in the recurrence kernel

// ---------------- scratch (device globals: allocation-free) ----------------
__device__ float g_xg[(size_t)2 * Mz * Gz];          // per-dir precomputed input gates (fp32)
__device__ float g_h0out[(size_t)Lz * Bz * 2 * Hz];  // layer-0 output [t][b][2H]
__device__ __half g_hf[2 * Bz * Hz];                 // running h per direction (fp16)
__device__ unsigned g_cnt[2];                        // barrier arrival counters
__device__ unsigned g_gen[2];                        // barrier generation
__device__ __half g_Af [(size_t)Mz * 1024];          // fp16 activations (single)
__device__ __half g_Whf[(size_t)2 * Gz * 1024];      // fp16 Wih hi
__device__ __half g_Wlf[(size_t)2 * Gz * 1024];      // fp16 Wih lo

// ======================= PTX helpers (base-ISA only) =======================
__device__ __forceinline__ uint32_t smem_to_u32(const void* p) {
    uint32_t a;
    asm("{ .reg .u64 t; cvta.to.shared.u64 t, %1; cvt.u32.u64 %0, t; }" : "=r"(a) : "l"(p));
    return a;
}
__device__ __forceinline__ void cpa16(uint32_t s, const void* g) {
    asm volatile("cp.async.cg.shared.global [%0], [%1], 16;" :: "r"(s), "l"(g));
}
__device__ __forceinline__ void ldsm_x4(uint32_t& r0, uint32_t& r1, uint32_t& r2, uint32_t& r3,
                                        uint32_t a) {
    asm volatile("ldmatrix.sync.aligned.m8n8.x4.shared.b16 {%0,%1,%2,%3}, [%4];"
                 : "=r"(r0), "=r"(r1), "=r"(r2), "=r"(r3) : "r"(a));
}
__device__ __forceinline__ void mma16816h(float* d, const uint32_t* a, const uint32_t* b) {
    asm volatile("mma.sync.aligned.m16n8k16.row.col.f32.f16.f16.f32 "
                 "{%0,%1,%2,%3}, {%4,%5,%6,%7}, {%8,%9}, {%0,%1,%2,%3};"
                 : "+f"(d[0]), "+f"(d[1]), "+f"(d[2]), "+f"(d[3])
                 : "r"(a[0]), "r"(a[1]), "r"(a[2]), "r"(a[3]), "r"(b[0]), "r"(b[1]));
}

// ============================================================================
// Conversion kernels
// ============================================================================
__global__ void conv_A_f16(const float* __restrict__ src, int layer, int kshift)
{
    const size_t i = ((size_t)blockIdx.x * 256 + threadIdx.x) * 4;
    const int K = 1 << kshift;
    const size_t m = i >> kshift;
    const size_t k = i & (size_t)(K - 1);
    float4 v;
    if (layer) v = *((const float4*)(g_h0out + (m << kshift) + k));
    else       v = *((const float4*)(src + ((m & 63) * 512 + (m >> 6)) * (size_t)K + k));
    __half2 p0 = __floats2half2_rn(v.x, v.y);
    __half2 p1 = __floats2half2_rn(v.z, v.w);
    *((__half2*)(g_Af + i))     = p0;
    *((__half2*)(g_Af + i + 2)) = p1;
}

__global__ void conv_W_f16(const float* __restrict__ Wf, const float* __restrict__ Wr, int K)
{
    const int dir = blockIdx.y;
    const size_t i = ((size_t)blockIdx.x * 256 + threadIdx.x) * 4;   // over 2048*K
    const float* src = dir ? Wr : Wf;
    const size_t off = (size_t)dir * Gz * K;
    const float4 v = *((const float4*)(src + i));
    __half h0 = __float2half_rn(v.x), h1 = __float2half_rn(v.y);
    __half h2 = __float2half_rn(v.z), h3 = __float2half_rn(v.w);
    __half l0 = __float2half_rn(v.x - __half2float(h0));
    __half l1 = __float2half_rn(v.y - __half2float(h1));
    __half l2 = __float2half_rn(v.z - __half2float(h2));
    __half l3 = __float2half_rn(v.w - __half2float(h3));
    *((__half2*)(g_Whf + off + i))     = __halves2half2(h0, h1);
    *((__half2*)(g_Whf + off + i + 2)) = __halves2half2(h2, h3);
    *((__half2*)(g_Wlf + off + i))     = __halves2half2(l0, l1);
    *((__half2*)(g_Wlf + off + i + 2)) = __halves2half2(l2, l3);
}

// ============================================================================
// mma.sync GEMM: Xg = bias + A @ W^T.  A fp16 single; W fp16 hi+lo (2 terms).
// CTA 128x128, BK=32, 8 warps (2Mx4N, warp tile 64x32), cp.async double-buffer.
// smem rows padded to 80B -> conflict-free ldmatrix.
// ============================================================================
#define TAH 0
#define TBH 10240
#define TBL 20480
#define BUFB 30720
#define GEMM_SMEM (2*BUFB)

__global__ void __launch_bounds__(256) gates_gemm_mma(
    const float* __restrict__ bi_f, const float* __restrict__ bh_f,
    const float* __restrict__ bi_r, const float* __restrict__ bh_r, int K)
{
    extern __shared__ char smem[];
    const uint32_t sb = smem_to_u32(smem);
    __shared__ float sBias[128];

    const int tid = threadIdx.x;
    const int wid = tid >> 5;
    const int lane = tid & 31;
    const int warpM = wid >> 2;       // 0..1
    const int warpN = wid & 3;        // 0..3
    const int dir = blockIdx.z;
    const int n0 = blockIdx.x * 128;
    const int m0 = blockIdx.y * 128;

    const __half* __restrict__ Wh = g_Whf + (size_t)dir * Gz * K;
    const __half* __restrict__ Wl = g_Wlf + (size_t)dir * Gz * K;
    const float* bi = dir ? bi_r : bi_f;
    const float* bh = dir ? bh_r : bh_f;
    if (tid < 128) sBias[tid] = bi[n0 + tid] + bh[n0 + tid];

    float acc[4][4][4];
#pragma unroll
    for (int mt = 0; mt < 4; mt++)
#pragma unroll
        for (int nt = 0; nt < 4; nt++)
#pragma unroll
            for (int q = 0; q < 4; q++) acc[mt][nt][q] = 0.f;

    const int lrow = tid >> 2;
    const int lseg = tid & 3;

#define LOAD_CHUNK(kc, boff) do { \
    _Pragma("unroll") \
    for (int i = 0; i < 2; i++) { \
        const int row = lrow + 64 * i; \
        const uint32_t so = (uint32_t)(row * 80 + lseg * 16); \
        const size_t ga = (size_t)(m0 + row) * K + (kc) + lseg * 8; \
        const size_t gb = (size_t)(n0 + row) * K + (kc) + lseg * 8; \
        cpa16(sb + (boff) + TAH + so, g_Af + ga); \
        cpa16(sb + (boff) + TBH + so, Wh + gb); \
        cpa16(sb + (boff) + TBL + so, Wl + gb); \
    } \
    asm volatile("cp.async.commit_group;" ::: "memory"); \
} while (0)

    const int nch = K >> 5;
    LOAD_CHUNK(0, 0);

    const int aRowOff = (lane & 7) + ((lane >> 3) & 1) * 8;
    const int aColOff = ((lane >> 4) & 1) * 16;
    const int bRowOff = (lane & 7) + ((lane >> 4) & 1) * 8;
    const int bColOff = ((lane >> 3) & 1) * 16;

    for (int ch = 0; ch < nch; ch++) {
        if (ch + 1 < nch) {
            LOAD_CHUNK((ch + 1) << 5, (uint32_t)(((ch + 1) & 1) * BUFB));
            asm volatile("cp.async.wait_group 1;" ::: "memory");
        } else {
            asm volatile("cp.async.wait_group 0;" ::: "memory");
        }
        __syncthreads();

        const uint32_t boff = sb + (uint32_t)((ch & 1) * BUFB);
#pragma unroll
        for (int ks = 0; ks < 2; ks++) {
            const int kb = ks * 32;
            uint32_t aH[4][4], bH[4][2], bL[4][2];
#pragma unroll
            for (int mt = 0; mt < 4; mt++) {
                const uint32_t ra = (uint32_t)((warpM * 64 + mt * 16 + aRowOff) * 80 + kb + aColOff);
                ldsm_x4(aH[mt][0], aH[mt][1], aH[mt][2], aH[mt][3], boff + TAH + ra);
            }
#pragma unroll
            for (int p = 0; p < 2; p++) {
                const uint32_t rb = (uint32_t)((warpN * 32 + p * 16 + bRowOff) * 80 + kb + bColOff);
                uint32_t r0, r1, r2, r3;
                ldsm_x4(r0, r1, r2, r3, boff + TBH + rb);
                bH[2*p][0] = r0; bH[2*p][1] = r1; bH[2*p+1][0] = r2; bH[2*p+1][1] = r3;
                ldsm_x4(r0, r1, r2, r3, boff + TBL + rb);
                bL[2*p][0] = r0; bL[2*p][1] = r1; bL[2*p+1][0] = r2; bL[2*p+1][1] = r3;
            }
#pragma unroll
            for (int mt = 0; mt < 4; mt++)
#pragma unroll
                for (int nt = 0; nt < 4; nt++) {
                    mma16816h(acc[mt][nt], aH[mt], bH[nt]);
                    mma16816h(acc[mt][nt], aH[mt], bL[nt]);
                }
        }
        __syncthreads();
    }

    float* __restrict__ outp = g_xg + (size_t)dir * Mz * Gz;
    const int g  = lane >> 2;
    const int tg = lane & 3;
#pragma unroll
    for (int mt = 0; mt < 4; mt++) {
        const int m = m0 + warpM * 64 + mt * 16 + g;
#pragma unroll
        for (int nt = 0; nt < 4; nt++) {
            const int nl = warpN * 32 + nt * 8 + tg * 2;
            const float b0 = sBias[nl], b1 = sBias[nl + 1];
            float2 v0 = make_float2(acc[mt][nt][0] + b0, acc[mt][nt][1] + b1);
            float2 v1 = make_float2(acc[mt][nt][2] + b0, acc[mt][nt][3] + b1);
            *((float2*)(outp + (size_t)m * Gz + n0 + nl)) = v0;
            *((float2*)(outp + (size_t)(m + 8) * Gz + n0 + nl)) = v1;
        }
    }
#undef LOAD_CHUNK
}

// ============================================================================
// Persistent recurrence v3: single-fp16 Whh HMMA + xg prefetch.
// 128 CTAs (64/dir), 256 thr. CTA cb owns h-cols [cb*8,cb*8+8) -> 32 gate cols.
// ============================================================================
__device__ __forceinline__ void grid_bar(int dir, unsigned target)
{
    __syncthreads();
    if (threadIdx.x == 0) {
        __threadfence();
        const unsigned prev = atomicAdd(&g_cnt[dir], 1u);
        if (prev == (unsigned)(NCD - 1)) {
            atomicExch(&g_cnt[dir], 0u);
            __threadfence();
            atomicExch(&g_gen[dir], target);
        } else {
            while (*((volatile unsigned*)&g_gen[dir]) != target) { }
        }
        __threadfence();
    }
    __syncthreads();
}

// dynamic smem layout (bytes)
#define RP 1040                   // row pitch: 520 halfs (512 + 8 pad)
#define SWH  0                    // [32][520] fp16   33280 B
#define SAH  33280                // [64][520] fp16   66560 B
#define SXG  99840                // 2 x [64][36] fp32  18432 B
#define XGB  9216                 // xg buffer stride
#define SGT  118272               // [64][34] fp32     8704 B
#define REC_SMEM 126976

__global__ void __launch_bounds__(256) lstm_recur_mma(
    const float* __restrict__ Whh_f, const float* __restrict__ Whh_r,
    float* __restrict__ dout, int layer)
{
    extern __shared__ char dsm[];
    const uint32_t sb = smem_to_u32(dsm);
    __shared__ unsigned s_base;

    const int dir = (int)(blockIdx.x) / NCD;
    const int cb  = (int)(blockIdx.x) % NCD;
    const float* __restrict__ W  = dir ? Whh_r : Whh_f;
    const float* __restrict__ xg = g_xg + (size_t)dir * Mz * Gz;
    __half* hb = g_hf + dir * Bz * Hz;
    float* outp = layer ? dout : (float*)g_h0out;
    const int ts = layer ? (2*Hz) : (Bz*2*Hz);
    const int bs = layer ? (Lz*2*Hz) : (2*Hz);

    const int tid = threadIdx.x;
    const int wid = tid >> 5;
    const int lane = tid & 31;
    const int warpM = wid & 3;        // 4 warps over M=64 (16 rows each)
    const int warpN = wid >> 2;       // 2 warps over N=32 (16 cols each)

    if (tid == 0) s_base = *((volatile unsigned*)&g_gen[dir]);

    // ---- stage Whh slice -> single fp16 in smem (one time) ----
    __half* sW = (__half*)(dsm + SWH);
#pragma unroll
    for (int i = 0; i < 16; i++) {
        const int idx = tid + 256 * i;       // 0..4095 over 32 rows x 128 float4
        const int n  = idx >> 7;             // local gate col 0..31
        const int f4 = idx & 127;
        const int gcol = (n >> 3) * Hz + cb * 8 + (n & 7);
        const float4 v = *((const float4*)(W + (size_t)gcol * Hz + f4 * 4));
        __half* ph = sW + n * 520 + f4 * 4;
        ph[0] = __float2half_rn(v.x); ph[1] = __float2half_rn(v.y);
        ph[2] = __float2half_rn(v.z); ph[3] = __float2half_rn(v.w);
    }

    // zero-init owned h columns (fp16)
#pragma unroll
    for (int r = 0; r < 2; r++) {
        const int id = tid + 256 * r;
        hb[(id >> 3) * Hz + cb * 8 + (id & 7)] = __float2half(0.f);
    }
    __syncthreads();
    const unsigned base = s_base;
    unsigned bar = 0;
    float creg[2] = {0.f, 0.f};
    grid_bar(dir, base + (++bar));   // h=0 visible everywhere

    const int aRowOff = (lane & 7) + ((lane >> 3) & 1) * 8;
    const int aColOff = ((lane >> 4) & 1) * 16;
    const int bRowOff = (lane & 7) + ((lane >> 4) & 1) * 8;
    const int bColOff = ((lane >> 3) & 1) * 16;

    float* sGf  = (float*)(dsm + SGT);   // [64][34]

    // xg prefetch helper: [64][32] fp32 per step, 512 cpa16 per CTA
#define XG_LOAD(t_, buf_) do { \
    _Pragma("unroll") \
    for (int i = 0; i < 2; i++) { \
        const int idx = tid + 256 * i; \
        const int b = idx >> 3, rem = idx & 7; \
        const int g = rem >> 1, q = rem & 1; \
        cpa16(sb + SXG + (buf_) * XGB + b * 144 + g * 32 + q * 16, \
              xg + ((size_t)(t_) * Bz + b) * Gz + g * Hz + cb * 8 + q * 4); \
    } \
    asm volatile("cp.async.commit_group;" ::: "memory"); \
} while (0)

    // prologue: xg for step 0 into buffer 0
    {
        const int t0 = dir ? (Lz - 1) : 0;
        XG_LOAD(t0, 0);
    }

    for (int s = 0; s < Lz; s++) {
        const int t = dir ? (Lz - 1 - s) : s;

        // ---- cp.async h tile: 64 rows x 1024B ----
#pragma unroll
        for (int i = 0; i < 16; i++) {
            const int idx = tid + 256 * i;   // 0..4095
            const int b = idx >> 6, seg = idx & 63;
            cpa16(sb + SAH + b * RP + seg * 16, hb + b * Hz + seg * 8);
        }
        asm volatile("cp.async.commit_group;" ::: "memory");

        // ---- prefetch next step's xg (independent of h) ----
        if (s + 1 < Lz) {
            const int tn = dir ? (Lz - 2 - s) : (s + 1);
            XG_LOAD(tn, (s + 1) & 1);
            asm volatile("cp.async.wait_group 1;" ::: "memory");
        } else {
            asm volatile("cp.async.wait_group 0;" ::: "memory");
        }
        __syncthreads();

        // ---- MMA: gates(64x32) = h(64x512) @ Wslice^T (single fp16 W) ----
        float acc0[4] = {0.f,0.f,0.f,0.f};
        float acc1[4] = {0.f,0.f,0.f,0.f};
        const uint32_t aBase = sb + SAH + (uint32_t)((warpM * 16 + aRowOff) * RP + aColOff);
        const uint32_t bBase = sb + SWH + (uint32_t)((warpN * 16 + bRowOff) * RP + bColOff);
#pragma unroll 8
        for (int ks = 0; ks < 32; ks++) {
            uint32_t a[4], bh[4];
            ldsm_x4(a[0], a[1], a[2], a[3], aBase + ks * 32);
            ldsm_x4(bh[0], bh[1], bh[2], bh[3], bBase + ks * 32);
            mma16816h(acc0, a, bh);
            mma16816h(acc1, a, bh + 2);
        }

        // ---- write frags to sG ----
        {
            const int g = lane >> 2, tg = lane & 3;
            const int r = warpM * 16 + g;
            const int c = warpN * 16 + tg * 2;
            *((float2*)(sGf + r * 34 + c))           = make_float2(acc0[0], acc0[1]);
            *((float2*)(sGf + (r + 8) * 34 + c))     = make_float2(acc0[2], acc0[3]);
            *((float2*)(sGf + r * 34 + c + 8))       = make_float2(acc1[0], acc1[1]);
            *((float2*)(sGf + (r + 8) * 34 + c + 8)) = make_float2(acc1[2], acc1[3]);
        }
        __syncthreads();

        // ---- elementwise LSTM cell ----
        const float* sXGf = (const float*)(dsm + SXG + (s & 1) * XGB);
#pragma unroll
        for (int r = 0; r < 2; r++) {
            const int id = tid + 256 * r;
            const int b = id >> 3, j = id & 7;
            const float iv = sGf[b*34 + j]      + sXGf[b*36 + j];
            const float fv = sGf[b*34 + 8 + j]  + sXGf[b*36 + 8 + j];
            const float gv = sGf[b*34 + 16 + j] + sXGf[b*36 + 16 + j];
            const float ov = sGf[b*34 + 24 + j] + sXGf[b*36 + 24 + j];
            const float ig = 1.f/(1.f + expf(-iv));
            const float fg = 1.f/(1.f + expf(-fv));
            const float og = 1.f/(1.f + expf(-ov));
            const float c  = fg*creg[r] + ig*tanhf(gv);
            const float hv = og*tanhf(c);
            creg[r] = c;
            const int hcol = cb*8 + j;
            hb[b*Hz + hcol] = __float2half(hv);
            outp[(size_t)t*ts + (size_t)b*bs + dir*Hz + hcol] = hv;
        }
        grid_bar(dir, base + (++bar));
    }
#undef XG_LOAD
}

// ============================================================================
// Launch sequence (graph-capturable, allocation-free)
// ============================================================================
extern "C" void kernel_launch(void* const* d_in, const int* in_sizes, int n_in,
                              void* d_out, int out_size)
{
    const float* x      = (const float*)d_in[0];
    const float* Wih_f0 = (const float*)d_in[1];
    const float* Whh_f0 = (const float*)d_in[2];
    const float* bih_f0 = (const float*)d_in[3];
    const float* bhh_f0 = (const float*)d_in[4];
    const float* Wih_r0 = (const float*)d_in[5];
    const float* Whh_r0 = (const float*)d_in[6];
    const float* bih_r0 = (const float*)d_in[7];
    const float* bhh_r0 = (const float*)d_in[8];
    const float* Wih_f1 = (const float*)d_in[9];
    const float* Whh_f1 = (const float*)d_in[10];
    const float* bih_f1 = (const float*)d_in[11];
    const float* bhh_f1 = (const float*)d_in[12];
    const float* Wih_r1 = (const float*)d_in[13];
    const float* Whh_r1 = (const float*)d_in[14];
    const float* bih_r1 = (const float*)d_in[15];
    const float* bhh_r1 = (const float*)d_in[16];
    float* outp = (float*)d_out;

    cudaFuncSetAttribute(gates_gemm_mma, cudaFuncAttributeMaxDynamicSharedMemorySize, GEMM_SMEM);
    cudaFuncSetAttribute(lstm_recur_mma, cudaFuncAttributeMaxDynamicSharedMemorySize, REC_SMEM);

    const dim3 gemm_grid(Gz/128, Mz/128, 2);     // (16, 256, 2)

    // ---- layer 0 (K = 256) ----
    conv_W_f16<<<dim3((Gz*256)/1024, 2), 256>>>(Wih_f0, Wih_r0, 256);
    conv_A_f16<<<(Mz*256)/1024, 256>>>(x, 0, 8);
    gates_gemm_mma<<<gemm_grid, 256, GEMM_SMEM>>>(bih_f0, bhh_f0, bih_r0, bhh_r0, 256);
    lstm_recur_mma<<<2*NCD, 256, REC_SMEM>>>(Whh_f0, Whh_r0, outp, 0);

    // ---- layer 1 (K = 1024) ----
    conv_W_f16<<<dim3((Gz*1024)/1024, 2), 256>>>(Wih_f1, Wih_r1, 1024);
    conv_A_f16<<<(Mz*1024)/1024, 256>>>(x, 1, 10);
    gates_gemm_mma<<<gemm_grid, 256, GEMM_SMEM>>>(bih_f1, bhh_f1, bih_r1, bhh_r1, 1024);
    lstm_recur_mma<<<2*NCD, 256, REC_SMEM>>>(Whh_f1, Whh_r1, outp, 1);
}

// round 6
// speedup vs baseline: 3.6853x; 1.1492x over previous
#include <cuda_runtime.h>
#include <cuda_fp16.h>
#include <math.h>
#include <stdint.h>

// Problem constants
#define Bz 64
#define Lz 512
#define Iz 256
#define Hz 512
#define Gz 2048           // 4*H
#define Mz (Lz*Bz)        // 32768
#define NCD 64            // CTAs per direction in the recurrence kernel

// ---------------- scratch (device globals: allocation-free) ----------------
__device__ float g_xg[(size_t)2 * Mz * Gz];          // per-dir precomputed input gates (fp32)
__device__ float g_h0out[(size_t)Lz * Bz * 2 * Hz];  // layer-0 output [t][b][2H]
__device__ __half g_hf[2 * Bz * Hz];                 // running h per direction (fp16)
__device__ unsigned g_cnt[2];                        // barrier arrival counters
__device__ unsigned g_gen[2];                        // barrier generation
__device__ __half g_Af [(size_t)Mz * 1024];          // fp16 activations (single)
__device__ __half g_Whf[(size_t)2 * Gz * 1024];      // fp16 Wih hi
__device__ __half g_Wlf[(size_t)2 * Gz * 1024];      // fp16 Wih lo

// ======================= PTX helpers (base-ISA only) =======================
__device__ __forceinline__ uint32_t smem_to_u32(const void* p) {
    uint32_t a;
    asm("{ .reg .u64 t; cvta.to.shared.u64 t, %1; cvt.u32.u64 %0, t; }" : "=r"(a) : "l"(p));
    return a;
}
__device__ __forceinline__ void cpa16(uint32_t s, const void* g) {
    asm volatile("cp.async.cg.shared.global [%0], [%1], 16;" :: "r"(s), "l"(g));
}
__device__ __forceinline__ void ldsm_x4(uint32_t& r0, uint32_t& r1, uint32_t& r2, uint32_t& r3,
                                        uint32_t a) {
    asm volatile("ldmatrix.sync.aligned.m8n8.x4.shared.b16 {%0,%1,%2,%3}, [%4];"
                 : "=r"(r0), "=r"(r1), "=r"(r2), "=r"(r3) : "r"(a));
}
__device__ __forceinline__ void mma16816h(float* d, const uint32_t* a, const uint32_t* b) {
    asm volatile("mma.sync.aligned.m16n8k16.row.col.f32.f16.f16.f32 "
                 "{%0,%1,%2,%3}, {%4,%5,%6,%7}, {%8,%9}, {%0,%1,%2,%3};"
                 : "+f"(d[0]), "+f"(d[1]), "+f"(d[2]), "+f"(d[3])
                 : "r"(a[0]), "r"(a[1]), "r"(a[2]), "r"(a[3]), "r"(b[0]), "r"(b[1]));
}
// fast activations (clamped; rel err ~2^-21, negligible vs 2.5e-4 budget)
__device__ __forceinline__ float sigf(float x) {
    return __fdividef(1.f, 1.f + __expf(-x));
}
__device__ __forceinline__ float tanhf_fast(float x) {
    x = fminf(15.f, fmaxf(-15.f, x));
    const float e = __expf(-2.f * x);
    return __fdividef(1.f - e, 1.f + e);
}

// ============================================================================
// Conversion kernels
// ============================================================================
__global__ void conv_A_f16(const float* __restrict__ src, int layer, int kshift)
{
    const size_t i = ((size_t)blockIdx.x * 256 + threadIdx.x) * 4;
    const int K = 1 << kshift;
    const size_t m = i >> kshift;
    const size_t k = i & (size_t)(K - 1);
    float4 v;
    if (layer) v = *((const float4*)(g_h0out + (m << kshift) + k));
    else       v = *((const float4*)(src + ((m & 63) * 512 + (m >> 6)) * (size_t)K + k));
    *((__half2*)(g_Af + i))     = __floats2half2_rn(v.x, v.y);
    *((__half2*)(g_Af + i + 2)) = __floats2half2_rn(v.z, v.w);
}

__global__ void conv_W_f16(const float* __restrict__ Wf, const float* __restrict__ Wr, int K)
{
    const int dir = blockIdx.y;
    const size_t i = ((size_t)blockIdx.x * 256 + threadIdx.x) * 4;   // over 2048*K
    const float* src = dir ? Wr : Wf;
    const size_t off = (size_t)dir * Gz * K;
    const float4 v = *((const float4*)(src + i));
    __half h0 = __float2half_rn(v.x), h1 = __float2half_rn(v.y);
    __half h2 = __float2half_rn(v.z), h3 = __float2half_rn(v.w);
    __half l0 = __float2half_rn(v.x - __half2float(h0));
    __half l1 = __float2half_rn(v.y - __half2float(h1));
    __half l2 = __float2half_rn(v.z - __half2float(h2));
    __half l3 = __float2half_rn(v.w - __half2float(h3));
    *((__half2*)(g_Whf + off + i))     = __halves2half2(h0, h1);
    *((__half2*)(g_Whf + off + i + 2)) = __halves2half2(h2, h3);
    *((__half2*)(g_Wlf + off + i))     = __halves2half2(l0, l1);
    *((__half2*)(g_Wlf + off + i + 2)) = __halves2half2(l2, l3);
}

// ============================================================================
// mma.sync GEMM: Xg = bias + A @ W^T.  A fp16 single; W fp16 hi+lo (2 terms).
// CTA 128x128, BK=32, 8 warps (2Mx4N), cp.async 3-STAGE pipeline.
// smem rows padded to 80B -> conflict-free ldmatrix.
// ============================================================================
#define TAH 0
#define TBH 10240
#define TBL 20480
#define BUFB 30720
#define GEMM_SMEM (3*BUFB)

__global__ void __launch_bounds__(256) gates_gemm_mma(
    const float* __restrict__ bi_f, const float* __restrict__ bh_f,
    const float* __restrict__ bi_r, const float* __restrict__ bh_r, int K)
{
    extern __shared__ char smem[];
    const uint32_t sb = smem_to_u32(smem);
    __shared__ float sBias[128];

    const int tid = threadIdx.x;
    const int wid = tid >> 5;
    const int lane = tid & 31;
    const int warpM = wid >> 2;       // 0..1
    const int warpN = wid & 3;        // 0..3
    const int dir = blockIdx.z;
    const int n0 = blockIdx.x * 128;
    const int m0 = blockIdx.y * 128;

    const __half* __restrict__ Wh = g_Whf + (size_t)dir * Gz * K;
    const __half* __restrict__ Wl = g_Wlf + (size_t)dir * Gz * K;
    const float* bi = dir ? bi_r : bi_f;
    const float* bh = dir ? bh_r : bh_f;
    if (tid < 128) sBias[tid] = bi[n0 + tid] + bh[n0 + tid];

    float acc[4][4][4];
#pragma unroll
    for (int mt = 0; mt < 4; mt++)
#pragma unroll
        for (int nt = 0; nt < 4; nt++)
#pragma unroll
            for (int q = 0; q < 4; q++) acc[mt][nt][q] = 0.f;

    const int lrow = tid >> 2;
    const int lseg = tid & 3;

#define LOAD_CHUNK(kc, boff) do { \
    _Pragma("unroll") \
    for (int i = 0; i < 2; i++) { \
        const int row = lrow + 64 * i; \
        const uint32_t so = (uint32_t)(row * 80 + lseg * 16); \
        const size_t ga = (size_t)(m0 + row) * K + (kc) + lseg * 8; \
        const size_t gb = (size_t)(n0 + row) * K + (kc) + lseg * 8; \
        cpa16(sb + (boff) + TAH + so, g_Af + ga); \
        cpa16(sb + (boff) + TBH + so, Wh + gb); \
        cpa16(sb + (boff) + TBL + so, Wl + gb); \
    } \
    asm volatile("cp.async.commit_group;" ::: "memory"); \
} while (0)

    const int nch = K >> 5;
    // preload 2 chunks (3 buffers rotate)
    LOAD_CHUNK(0, 0);
    LOAD_CHUNK(32, BUFB);

    const int aRowOff = (lane & 7) + ((lane >> 3) & 1) * 8;
    const int aColOff = ((lane >> 4) & 1) * 16;
    const int bRowOff = (lane & 7) + ((lane >> 4) & 1) * 8;
    const int bColOff = ((lane >> 3) & 1) * 16;

    int buf = 0;
    for (int ch = 0; ch < nch; ch++) {
        if (ch + 1 < nch) asm volatile("cp.async.wait_group 1;" ::: "memory");
        else              asm volatile("cp.async.wait_group 0;" ::: "memory");
        __syncthreads();

        const uint32_t boff = sb + (uint32_t)(buf * BUFB);
#pragma unroll
        for (int ks = 0; ks < 2; ks++) {
            const int kb = ks * 32;
            uint32_t aH[4][4], bH[4][2], bL[4][2];
#pragma unroll
            for (int mt = 0; mt < 4; mt++) {
                const uint32_t ra = (uint32_t)((warpM * 64 + mt * 16 + aRowOff) * 80 + kb + aColOff);
                ldsm_x4(aH[mt][0], aH[mt][1], aH[mt][2], aH[mt][3], boff + TAH + ra);
            }
#pragma unroll
            for (int p = 0; p < 2; p++) {
                const uint32_t rb = (uint32_t)((warpN * 32 + p * 16 + bRowOff) * 80 + kb + bColOff);
                uint32_t r0, r1, r2, r3;
                ldsm_x4(r0, r1, r2, r3, boff + TBH + rb);
                bH[2*p][0] = r0; bH[2*p][1] = r1; bH[2*p+1][0] = r2; bH[2*p+1][1] = r3;
                ldsm_x4(r0, r1, r2, r3, boff + TBL + rb);
                bL[2*p][0] = r0; bL[2*p][1] = r1; bL[2*p+1][0] = r2; bL[2*p+1][1] = r3;
            }
#pragma unroll
            for (int mt = 0; mt < 4; mt++)
#pragma unroll
                for (int nt = 0; nt < 4; nt++) {
                    mma16816h(acc[mt][nt], aH[mt], bH[nt]);
                    mma16816h(acc[mt][nt], aH[mt], bL[nt]);
                }
        }
        // issue load for ch+2 into the buffer freed 2 iterations ago
        if (ch + 2 < nch) {
            const int nb = (buf + 2) % 3;
            LOAD_CHUNK((ch + 2) << 5, (uint32_t)(nb * BUFB));
        }
        buf = (buf + 1) % 3;
    }

    float* __restrict__ outp = g_xg + (size_t)dir * Mz * Gz;
    const int g  = lane >> 2;
    const int tg = lane & 3;
#pragma unroll
    for (int mt = 0; mt < 4; mt++) {
        const int m = m0 + warpM * 64 + mt * 16 + g;
#pragma unroll
        for (int nt = 0; nt < 4; nt++) {
            const int nl = warpN * 32 + nt * 8 + tg * 2;
            const float b0 = sBias[nl], b1 = sBias[nl + 1];
            float2 v0 = make_float2(acc[mt][nt][0] + b0, acc[mt][nt][1] + b1);
            float2 v1 = make_float2(acc[mt][nt][2] + b0, acc[mt][nt][3] + b1);
            *((float2*)(outp + (size_t)m * Gz + n0 + nl)) = v0;
            *((float2*)(outp + (size_t)(m + 8) * Gz + n0 + nl)) = v1;
        }
    }
#undef LOAD_CHUNK
}

// ============================================================================
// Persistent recurrence v4: chunked h-load/MMA overlap + fast activations.
// 128 CTAs (64/dir), 256 thr. CTA cb owns h-cols [cb*8,cb*8+8) -> 32 gate cols.
// ============================================================================
__device__ __forceinline__ void grid_bar(int dir, unsigned target)
{
    __syncthreads();
    if (threadIdx.x == 0) {
        __threadfence();
        const unsigned prev = atomicAdd(&g_cnt[dir], 1u);
        if (prev == (unsigned)(NCD - 1)) {
            atomicExch(&g_cnt[dir], 0u);
            __threadfence();
            atomicExch(&g_gen[dir], target);
        } else {
            while (*((volatile unsigned*)&g_gen[dir]) != target) { }
        }
        __threadfence();
    }
    __syncthreads();
}

// dynamic smem layout (bytes)
#define RP 1040                   // row pitch: 520 halfs (512 + 8 pad)
#define SWH  0                    // [32][520] fp16   33280 B
#define SAH  33280                // [64][520] fp16   66560 B
#define SXG  99840                // 2 x [64][36] fp32  18432 B
#define XGB  9216                 // xg buffer stride
#define SGT  118272               // [64][34] fp32     8704 B
#define REC_SMEM 126976

__global__ void __launch_bounds__(256) lstm_recur_mma(
    const float* __restrict__ Whh_f, const float* __restrict__ Whh_r,
    float* __restrict__ dout, int layer)
{
    extern __shared__ char dsm[];
    const uint32_t sb = smem_to_u32(dsm);
    __shared__ unsigned s_base;

    const int dir = (int)(blockIdx.x) / NCD;
    const int cb  = (int)(blockIdx.x) % NCD;
    const float* __restrict__ W  = dir ? Whh_r : Whh_f;
    const float* __restrict__ xg = g_xg + (size_t)dir * Mz * Gz;
    __half* hb = g_hf + dir * Bz * Hz;
    float* outp = layer ? dout : (float*)g_h0out;
    const int ts = layer ? (2*Hz) : (Bz*2*Hz);
    const int bs = layer ? (Lz*2*Hz) : (2*Hz);

    const int tid = threadIdx.x;
    const int wid = tid >> 5;
    const int lane = tid & 31;
    const int warpM = wid & 3;        // 4 warps over M=64 (16 rows each)
    const int warpN = wid >> 2;       // 2 warps over N=32 (16 cols each)

    if (tid == 0) s_base = *((volatile unsigned*)&g_gen[dir]);

    // ---- stage Whh slice -> single fp16 in smem (one time) ----
    __half* sW = (__half*)(dsm + SWH);
#pragma unroll
    for (int i = 0; i < 16; i++) {
        const int idx = tid + 256 * i;       // 0..4095 over 32 rows x 128 float4
        const int n  = idx >> 7;             // local gate col 0..31
        const int f4 = idx & 127;
        const int gcol = (n >> 3) * Hz + cb * 8 + (n & 7);
        const float4 v = *((const float4*)(W + (size_t)gcol * Hz + f4 * 4));
        __half* ph = sW + n * 520 + f4 * 4;
        ph[0] = __float2half_rn(v.x); ph[1] = __float2half_rn(v.y);
        ph[2] = __float2half_rn(v.z); ph[3] = __float2half_rn(v.w);
    }

    // zero-init owned h columns (fp16)
#pragma unroll
    for (int r = 0; r < 2; r++) {
        const int id = tid + 256 * r;
        hb[(id >> 3) * Hz + cb * 8 + (id & 7)] = __float2half(0.f);
    }
    __syncthreads();
    const unsigned base = s_base;
    unsigned bar = 0;
    float creg[2] = {0.f, 0.f};
    grid_bar(dir, base + (++bar));   // h=0 visible everywhere

    const int aRowOff = (lane & 7) + ((lane >> 3) & 1) * 8;
    const int aColOff = ((lane >> 4) & 1) * 16;
    const int bRowOff = (lane & 7) + ((lane >> 4) & 1) * 8;
    const int bColOff = ((lane >> 3) & 1) * 16;

    float* sGf = (float*)(dsm + SGT);   // [64][34]

    // xg load: [64][32] fp32 per step (its own commit group)
#define XG_LOAD(t_, buf_) do { \
    _Pragma("unroll") \
    for (int i = 0; i < 2; i++) { \
        const int idx = tid + 256 * i; \
        const int b = idx >> 3, rem = idx & 7; \
        const int g = rem >> 1, q = rem & 1; \
        cpa16(sb + SXG + (buf_) * XGB + b * 144 + g * 32 + q * 16, \
              xg + ((size_t)(t_) * Bz + b) * Gz + g * Hz + cb * 8 + q * 4); \
    } \
    asm volatile("cp.async.commit_group;" ::: "memory"); \
} while (0)
    // h half-tile load: 64 rows x 512B (cols [c0*256, c0*256+256))
#define H_LOAD(c0_) do { \
    _Pragma("unroll") \
    for (int i = 0; i < 8; i++) { \
        const int idx = tid + 256 * i;   /* 0..2047 */ \
        const int b = idx >> 5, seg = (idx & 31) + (c0_) * 32; \
        cpa16(sb + SAH + b * RP + seg * 16, hb + b * Hz + seg * 8); \
    } \
    asm volatile("cp.async.commit_group;" ::: "memory"); \
} while (0)

    // prologue: xg for step 0 into buffer 0
    {
        const int t0 = dir ? (Lz - 1) : 0;
        XG_LOAD(t0, 0);
    }

    for (int s = 0; s < Lz; s++) {
        const int t = dir ? (Lz - 1 - s) : s;

        // issue: h chunk0, h chunk1, next xg (3 groups)
        H_LOAD(0);
        H_LOAD(1);
        if (s + 1 < Lz) {
            const int tn = dir ? (Lz - 2 - s) : (s + 1);
            XG_LOAD(tn, (s + 1) & 1);
        }

        const uint32_t aBase = sb + SAH + (uint32_t)((warpM * 16 + aRowOff) * RP + aColOff);
        const uint32_t bBase = sb + SWH + (uint32_t)((warpN * 16 + bRowOff) * RP + bColOff);
        float acc0[4] = {0.f,0.f,0.f,0.f};
        float acc1[4] = {0.f,0.f,0.f,0.f};

        // wait: prior xg + h chunk0 done (allow h1 + next-xg pending)
        asm volatile("cp.async.wait_group 2;" ::: "memory");
        __syncthreads();
#pragma unroll
        for (int ks = 0; ks < 16; ks++) {
            uint32_t a[4], bh[4];
            ldsm_x4(a[0], a[1], a[2], a[3], aBase + ks * 32);
            ldsm_x4(bh[0], bh[1], bh[2], bh[3], bBase + ks * 32);
            mma16816h(acc0, a, bh);
            mma16816h(acc1, a, bh + 2);
        }
        // wait: h chunk1 done (allow next-xg pending)
        if (s + 1 < Lz) asm volatile("cp.async.wait_group 1;" ::: "memory");
        else            asm volatile("cp.async.wait_group 0;" ::: "memory");
        __syncthreads();
#pragma unroll
        for (int ks = 16; ks < 32; ks++) {
            uint32_t a[4], bh[4];
            ldsm_x4(a[0], a[1], a[2], a[3], aBase + ks * 32);
            ldsm_x4(bh[0], bh[1], bh[2], bh[3], bBase + ks * 32);
            mma16816h(acc0, a, bh);
            mma16816h(acc1, a, bh + 2);
        }

        // ---- write frags to sG ----
        {
            const int g = lane >> 2, tg = lane & 3;
            const int r = warpM * 16 + g;
            const int c = warpN * 16 + tg * 2;
            *((float2*)(sGf + r * 34 + c))           = make_float2(acc0[0], acc0[1]);
            *((float2*)(sGf + (r + 8) * 34 + c))     = make_float2(acc0[2], acc0[3]);
            *((float2*)(sGf + r * 34 + c + 8))       = make_float2(acc1[0], acc1[1]);
            *((float2*)(sGf + (r + 8) * 34 + c + 8)) = make_float2(acc1[2], acc1[3]);
        }
        __syncthreads();

        // ---- elementwise LSTM cell (fast activations) ----
        const float* sXGf = (const float*)(dsm + SXG + (s & 1) * XGB);
#pragma unroll
        for (int r = 0; r < 2; r++) {
            const int id = tid + 256 * r;
            const int b = id >> 3, j = id & 7;
            const float iv = sGf[b*34 + j]      + sXGf[b*36 + j];
            const float fv = sGf[b*34 + 8 + j]  + sXGf[b*36 + 8 + j];
            const float gv = sGf[b*34 + 16 + j] + sXGf[b*36 + 16 + j];
            const float ov = sGf[b*34 + 24 + j] + sXGf[b*36 + 24 + j];
            const float c  = sigf(fv)*creg[r] + sigf(iv)*tanhf_fast(gv);
            const float hv = sigf(ov)*tanhf_fast(c);
            creg[r] = c;
            const int hcol = cb*8 + j;
            hb[b*Hz + hcol] = __float2half(hv);
            outp[(size_t)t*ts + (size_t)b*bs + dir*Hz + hcol] = hv;
        }
        grid_bar(dir, base + (++bar));
    }
#undef XG_LOAD
#undef H_LOAD
}

// ============================================================================
// Launch sequence (graph-capturable, allocation-free)
// ============================================================================
extern "C" void kernel_launch(void* const* d_in, const int* in_sizes, int n_in,
                              void* d_out, int out_size)
{
    const float* x      = (const float*)d_in[0];
    const float* Wih_f0 = (const float*)d_in[1];
    const float* Whh_f0 = (const float*)d_in[2];
    const float* bih_f0 = (const float*)d_in[3];
    const float* bhh_f0 = (const float*)d_in[4];
    const float* Wih_r0 = (const float*)d_in[5];
    const float* Whh_r0 = (const float*)d_in[6];
    const float* bih_r0 = (const float*)d_in[7];
    const float* bhh_r0 = (const float*)d_in[8];
    const float* Wih_f1 = (const float*)d_in[9];
    const float* Whh_f1 = (const float*)d_in[10];
    const float* bih_f1 = (const float*)d_in[11];
    const float* bhh_f1 = (const float*)d_in[12];
    const float* Wih_r1 = (const float*)d_in[13];
    const float* Whh_r1 = (const float*)d_in[14];
    const float* bih_r1 = (const float*)d_in[15];
    const float* bhh_r1 = (const float*)d_in[16];
    float* outp = (float*)d_out;

    cudaFuncSetAttribute(gates_gemm_mma, cudaFuncAttributeMaxDynamicSharedMemorySize, GEMM_SMEM);
    cudaFuncSetAttribute(lstm_recur_mma, cudaFuncAttributeMaxDynamicSharedMemorySize, REC_SMEM);

    const dim3 gemm_grid(Gz/128, Mz/128, 2);     // (16, 256, 2)

    // ---- layer 0 (K = 256) ----
    conv_W_f16<<<dim3((Gz*256)/1024, 2), 256>>>(Wih_f0, Wih_r0, 256);
    conv_A_f16<<<(Mz*256)/1024, 256>>>(x, 0, 8);
    gates_gemm_mma<<<gemm_grid, 256, GEMM_SMEM>>>(bih_f0, bhh_f0, bih_r0, bhh_r0, 256);
    lstm_recur_mma<<<2*NCD, 256, REC_SMEM>>>(Whh_f0, Whh_r0, outp, 0);

    // ---- layer 1 (K = 1024) ----
    conv_W_f16<<<dim3((Gz*1024)/1024, 2), 256>>>(Wih_f1, Wih_r1, 1024);
    conv_A_f16<<<(Mz*1024)/1024, 256>>>(x, 1, 10);
    gates_gemm_mma<<<gemm_grid, 256, GEMM_SMEM>>>(bih_f1, bhh_f1, bih_r1, bhh_r1, 1024);
    lstm_recur_mma<<<2*NCD, 256, REC_SMEM>>>(Whh_f1, Whh_r1, outp, 1);
}

// round 7
// speedup vs baseline: 3.7985x; 1.0307x over previous
#include <cuda_runtime.h>
#include <cuda_fp16.h>
#include <math.h>
#include <stdint.h>

// Problem constants
#define Bz 64
#define Lz 512
#define Iz 256
#define Hz 512
#define Gz 2048           // 4*H
#define Mz (Lz*Bz)        // 32768
#define NCD 64            // CTAs per direction in the recurrence kernel

// ---------------- scratch (device globals: allocation-free) ----------------
__device__ float g_xg[(size_t)2 * Mz * Gz];          // per-dir precomputed input gates (fp32)
__device__ float g_h0out[(size_t)Lz * Bz * 2 * Hz];  // layer-0 output [t][b][2H]
__device__ __half g_hf[2 * Bz * Hz];                 // running h per direction (fp16)
__device__ unsigned g_cnt[2];                        // barrier arrival counters
__device__ unsigned g_gen[2];                        // barrier generation
__device__ __half g_Af [(size_t)Mz * 1024];          // fp16 activations (single)
__device__ __half g_Whf[(size_t)2 * Gz * 1024];      // fp16 Wih hi
__device__ __half g_Wlf[(size_t)2 * Gz * 1024];      // fp16 Wih lo

// ======================= PTX helpers (base-ISA only) =======================
__device__ __forceinline__ uint32_t smem_to_u32(const void* p) {
    uint32_t a;
    asm("{ .reg .u64 t; cvta.to.shared.u64 t, %1; cvt.u32.u64 %0, t; }" : "=r"(a) : "l"(p));
    return a;
}
__device__ __forceinline__ void cpa16(uint32_t s, const void* g) {
    asm volatile("cp.async.cg.shared.global [%0], [%1], 16;" :: "r"(s), "l"(g));
}
__device__ __forceinline__ void ldsm_x4(uint32_t& r0, uint32_t& r1, uint32_t& r2, uint32_t& r3,
                                        uint32_t a) {
    asm volatile("ldmatrix.sync.aligned.m8n8.x4.shared.b16 {%0,%1,%2,%3}, [%4];"
                 : "=r"(r0), "=r"(r1), "=r"(r2), "=r"(r3) : "r"(a));
}
__device__ __forceinline__ void mma16816h(float* d, const uint32_t* a, const uint32_t* b) {
    asm volatile("mma.sync.aligned.m16n8k16.row.col.f32.f16.f16.f32 "
                 "{%0,%1,%2,%3}, {%4,%5,%6,%7}, {%8,%9}, {%0,%1,%2,%3};"
                 : "+f"(d[0]), "+f"(d[1]), "+f"(d[2]), "+f"(d[3])
                 : "r"(a[0]), "r"(a[1]), "r"(a[2]), "r"(a[3]), "r"(b[0]), "r"(b[1]));
}
// fast sigmoid (tanh stays exact for precision margin)
__device__ __forceinline__ float sigf(float x) {
    return __fdividef(1.f, 1.f + __expf(-x));
}

// ============================================================================
// Conversion kernels
// ============================================================================
__global__ void conv_A_f16(const float* __restrict__ src, int layer, int kshift)
{
    const size_t i = ((size_t)blockIdx.x * 256 + threadIdx.x) * 4;
    const int K = 1 << kshift;
    const size_t m = i >> kshift;
    const size_t k = i & (size_t)(K - 1);
    float4 v;
    if (layer) v = *((const float4*)(g_h0out + (m << kshift) + k));
    else       v = *((const float4*)(src + ((m & 63) * 512 + (m >> 6)) * (size_t)K + k));
    *((__half2*)(g_Af + i))     = __floats2half2_rn(v.x, v.y);
    *((__half2*)(g_Af + i + 2)) = __floats2half2_rn(v.z, v.w);
}

__global__ void conv_W_f16(const float* __restrict__ Wf, const float* __restrict__ Wr, int K)
{
    const int dir = blockIdx.y;
    const size_t i = ((size_t)blockIdx.x * 256 + threadIdx.x) * 4;   // over 2048*K
    const float* src = dir ? Wr : Wf;
    const size_t off = (size_t)dir * Gz * K;
    const float4 v = *((const float4*)(src + i));
    __half h0 = __float2half_rn(v.x), h1 = __float2half_rn(v.y);
    __half h2 = __float2half_rn(v.z), h3 = __float2half_rn(v.w);
    __half l0 = __float2half_rn(v.x - __half2float(h0));
    __half l1 = __float2half_rn(v.y - __half2float(h1));
    __half l2 = __float2half_rn(v.z - __half2float(h2));
    __half l3 = __float2half_rn(v.w - __half2float(h3));
    *((__half2*)(g_Whf + off + i))     = __halves2half2(h0, h1);
    *((__half2*)(g_Whf + off + i + 2)) = __halves2half2(h2, h3);
    *((__half2*)(g_Wlf + off + i))     = __halves2half2(l0, l1);
    *((__half2*)(g_Wlf + off + i + 2)) = __halves2half2(l2, l3);
}

// ============================================================================
// mma.sync GEMM: Xg = bias + A @ W^T.  A fp16 single; W fp16 hi+lo (2 terms).
// CTA 256x128, BK=32, 8 warps (4Mx2N; warp tile 64x64), cp.async 3-stage.
// smem rows padded to 80B -> conflict-free ldmatrix.
// ============================================================================
#define TAH 0
#define TBH 20480
#define TBL 30720
#define BUFB 40960
#define GEMM_SMEM (3*BUFB)

__global__ void __launch_bounds__(256) gates_gemm_mma(
    const float* __restrict__ bi_f, const float* __restrict__ bh_f,
    const float* __restrict__ bi_r, const float* __restrict__ bh_r, int K)
{
    extern __shared__ char smem[];
    const uint32_t sb = smem_to_u32(smem);
    __shared__ float sBias[128];

    const int tid = threadIdx.x;
    const int wid = tid >> 5;
    const int lane = tid & 31;
    const int warpM = wid >> 1;       // 0..3 (64 rows each)
    const int warpN = wid & 1;        // 0..1 (64 cols each)
    const int dir = blockIdx.z;
    const int n0 = blockIdx.x * 128;
    const int m0 = blockIdx.y * 256;

    const __half* __restrict__ Wh = g_Whf + (size_t)dir * Gz * K;
    const __half* __restrict__ Wl = g_Wlf + (size_t)dir * Gz * K;
    const float* bi = dir ? bi_r : bi_f;
    const float* bh = dir ? bh_r : bh_f;
    if (tid < 128) sBias[tid] = bi[n0 + tid] + bh[n0 + tid];

    float acc[4][8][4];
#pragma unroll
    for (int mt = 0; mt < 4; mt++)
#pragma unroll
        for (int nt = 0; nt < 8; nt++)
#pragma unroll
            for (int q = 0; q < 4; q++) acc[mt][nt][q] = 0.f;

#define LOAD_CHUNK(kc, boff) do { \
    _Pragma("unroll") \
    for (int i = 0; i < 4; i++) {  /* A: 256 rows x 64B */ \
        const int row = (tid >> 2) + 64 * i; \
        const uint32_t so = (uint32_t)(row * 80 + (tid & 3) * 16); \
        cpa16(sb + (boff) + TAH + so, g_Af + (size_t)(m0 + row) * K + (kc) + (tid & 3) * 8); \
    } \
    _Pragma("unroll") \
    for (int i = 0; i < 2; i++) {  /* B hi+lo: 128 rows x 64B each */ \
        const int idx = tid + 256 * i; \
        const int row = idx >> 2, seg = idx & 3; \
        const uint32_t so = (uint32_t)(row * 80 + seg * 16); \
        const size_t gb = (size_t)(n0 + row) * K + (kc) + seg * 8; \
        cpa16(sb + (boff) + TBH + so, Wh + gb); \
        cpa16(sb + (boff) + TBL + so, Wl + gb); \
    } \
    asm volatile("cp.async.commit_group;" ::: "memory"); \
} while (0)

    const int nch = K >> 5;
    LOAD_CHUNK(0, 0);
    LOAD_CHUNK(32, BUFB);

    const int aRowOff = (lane & 7) + ((lane >> 3) & 1) * 8;
    const int aColOff = ((lane >> 4) & 1) * 16;
    const int bRowOff = (lane & 7) + ((lane >> 4) & 1) * 8;
    const int bColOff = ((lane >> 3) & 1) * 16;

    int buf = 0;
    for (int ch = 0; ch < nch; ch++) {
        if (ch + 1 < nch) asm volatile("cp.async.wait_group 1;" ::: "memory");
        else              asm volatile("cp.async.wait_group 0;" ::: "memory");
        __syncthreads();

        const uint32_t boff = sb + (uint32_t)(buf * BUFB);
#pragma unroll
        for (int ks = 0; ks < 2; ks++) {
            const int kb = ks * 32;
            uint32_t aH[4][4], bH[8][2], bL[8][2];
#pragma unroll
            for (int mt = 0; mt < 4; mt++) {
                const uint32_t ra = (uint32_t)((warpM * 64 + mt * 16 + aRowOff) * 80 + kb + aColOff);
                ldsm_x4(aH[mt][0], aH[mt][1], aH[mt][2], aH[mt][3], boff + TAH + ra);
            }
#pragma unroll
            for (int p = 0; p < 4; p++) {
                const uint32_t rb = (uint32_t)((warpN * 64 + p * 16 + bRowOff) * 80 + kb + bColOff);
                uint32_t r0, r1, r2, r3;
                ldsm_x4(r0, r1, r2, r3, boff + TBH + rb);
                bH[2*p][0] = r0; bH[2*p][1] = r1; bH[2*p+1][0] = r2; bH[2*p+1][1] = r3;
                ldsm_x4(r0, r1, r2, r3, boff + TBL + rb);
                bL[2*p][0] = r0; bL[2*p][1] = r1; bL[2*p+1][0] = r2; bL[2*p+1][1] = r3;
            }
#pragma unroll
            for (int mt = 0; mt < 4; mt++)
#pragma unroll
                for (int nt = 0; nt < 8; nt++) {
                    mma16816h(acc[mt][nt], aH[mt], bH[nt]);
                    mma16816h(acc[mt][nt], aH[mt], bL[nt]);
                }
        }
        if (ch + 2 < nch) {
            const int nb = (buf + 2) % 3;
            LOAD_CHUNK((ch + 2) << 5, (uint32_t)(nb * BUFB));
        }
        buf = (buf + 1) % 3;
    }

    float* __restrict__ outp = g_xg + (size_t)dir * Mz * Gz;
    const int g  = lane >> 2;
    const int tg = lane & 3;
#pragma unroll
    for (int mt = 0; mt < 4; mt++) {
        const int m = m0 + warpM * 64 + mt * 16 + g;
#pragma unroll
        for (int nt = 0; nt < 8; nt++) {
            const int nl = warpN * 64 + nt * 8 + tg * 2;
            const float b0 = sBias[nl], b1 = sBias[nl + 1];
            float2 v0 = make_float2(acc[mt][nt][0] + b0, acc[mt][nt][1] + b1);
            float2 v1 = make_float2(acc[mt][nt][2] + b0, acc[mt][nt][3] + b1);
            *((float2*)(outp + (size_t)m * Gz + n0 + nl)) = v0;
            *((float2*)(outp + (size_t)(m + 8) * Gz + n0 + nl)) = v1;
        }
    }
#undef LOAD_CHUNK
}

// ============================================================================
// Persistent recurrence v5: Whh fragments live in REGISTERS (step-invariant);
// per step only h-ldsm + HMMA. Chunked h overlap + xg prefetch retained.
// 128 CTAs (64/dir), 256 thr. CTA cb owns h-cols [cb*8,cb*8+8) -> 32 gate cols.
// ============================================================================
__device__ __forceinline__ void grid_bar(int dir, unsigned target)
{
    __syncthreads();
    if (threadIdx.x == 0) {
        __threadfence();
        const unsigned prev = atomicAdd(&g_cnt[dir], 1u);
        if (prev == (unsigned)(NCD - 1)) {
            atomicExch(&g_cnt[dir], 0u);
            __threadfence();
            atomicExch(&g_gen[dir], target);
        } else {
            while (*((volatile unsigned*)&g_gen[dir]) != target) { }
        }
        __threadfence();
    }
    __syncthreads();
}

// dynamic smem layout (bytes)
#define RP 1040                   // row pitch: 520 halfs (512 + 8 pad)
#define SWH  0                    // [32][520] fp16   33280 B (init staging only)
#define SAH  33280                // [64][520] fp16   66560 B
#define SXG  99840                // 2 x [64][36] fp32  18432 B
#define XGB  9216                 // xg buffer stride
#define SGT  118272               // [64][34] fp32     8704 B
#define REC_SMEM 126976

__global__ void __launch_bounds__(256) lstm_recur_mma(
    const float* __restrict__ Whh_f, const float* __restrict__ Whh_r,
    float* __restrict__ dout, int layer)
{
    extern __shared__ char dsm[];
    const uint32_t sb = smem_to_u32(dsm);
    __shared__ unsigned s_base;

    const int dir = (int)(blockIdx.x) / NCD;
    const int cb  = (int)(blockIdx.x) % NCD;
    const float* __restrict__ W  = dir ? Whh_r : Whh_f;
    const float* __restrict__ xg = g_xg + (size_t)dir * Mz * Gz;
    __half* hb = g_hf + dir * Bz * Hz;
    float* outp = layer ? dout : (float*)g_h0out;
    const int ts = layer ? (2*Hz) : (Bz*2*Hz);
    const int bs = layer ? (Lz*2*Hz) : (2*Hz);

    const int tid = threadIdx.x;
    const int wid = tid >> 5;
    const int lane = tid & 31;
    const int warpM = wid & 3;        // 4 warps over M=64 (16 rows each)
    const int warpN = wid >> 2;       // 2 warps over N=32 (16 cols each)

    if (tid == 0) s_base = *((volatile unsigned*)&g_gen[dir]);

    // ---- stage Whh slice -> fp16 smem (one time), then lift to registers ----
    __half* sW = (__half*)(dsm + SWH);
#pragma unroll
    for (int i = 0; i < 16; i++) {
        const int idx = tid + 256 * i;       // 0..4095 over 32 rows x 128 float4
        const int n  = idx >> 7;             // local gate col 0..31
        const int f4 = idx & 127;
        const int gcol = (n >> 3) * Hz + cb * 8 + (n & 7);
        const float4 v = *((const float4*)(W + (size_t)gcol * Hz + f4 * 4));
        __half* ph = sW + n * 520 + f4 * 4;
        ph[0] = __float2half_rn(v.x); ph[1] = __float2half_rn(v.y);
        ph[2] = __float2half_rn(v.z); ph[3] = __float2half_rn(v.w);
    }

    // zero-init owned h columns (fp16)
#pragma unroll
    for (int r = 0; r < 2; r++) {
        const int id = tid + 256 * r;
        hb[(id >> 3) * Hz + cb * 8 + (id & 7)] = __float2half(0.f);
    }
    __syncthreads();

    const int aRowOff = (lane & 7) + ((lane >> 3) & 1) * 8;
    const int aColOff = ((lane >> 4) & 1) * 16;
    const int bRowOff = (lane & 7) + ((lane >> 4) & 1) * 8;
    const int bColOff = ((lane >> 3) & 1) * 16;

    // W fragments -> registers (step-invariant): 32 ks x 4 regs
    uint32_t bw[32][4];
    {
        const uint32_t bBase = sb + SWH + (uint32_t)((warpN * 16 + bRowOff) * RP + bColOff);
#pragma unroll
        for (int ks = 0; ks < 32; ks++)
            ldsm_x4(bw[ks][0], bw[ks][1], bw[ks][2], bw[ks][3], bBase + ks * 32);
    }

    const unsigned base = s_base;
    unsigned bar = 0;
    float creg[2] = {0.f, 0.f};
    grid_bar(dir, base + (++bar));   // h=0 visible everywhere

    float* sGf = (float*)(dsm + SGT);   // [64][34]

#define XG_LOAD(t_, buf_) do { \
    _Pragma("unroll") \
    for (int i = 0; i < 2; i++) { \
        const int idx = tid + 256 * i; \
        const int b = idx >> 3, rem = idx & 7; \
        const int g = rem >> 1, q = rem & 1; \
        cpa16(sb + SXG + (buf_) * XGB + b * 144 + g * 32 + q * 16, \
              xg + ((size_t)(t_) * Bz + b) * Gz + g * Hz + cb * 8 + q * 4); \
    } \
    asm volatile("cp.async.commit_group;" ::: "memory"); \
} while (0)
#define H_LOAD(c0_) do { \
    _Pragma("unroll") \
    for (int i = 0; i < 8; i++) { \
        const int idx = tid + 256 * i;   /* 0..2047 */ \
        const int b = idx >> 5, seg = (idx & 31) + (c0_) * 32; \
        cpa16(sb + SAH + b * RP + seg * 16, hb + b * Hz + seg * 8); \
    } \
    asm volatile("cp.async.commit_group;" ::: "memory"); \
} while (0)

    // prologue: xg for step 0 into buffer 0
    {
        const int t0 = dir ? (Lz - 1) : 0;
        XG_LOAD(t0, 0);
    }

    for (int s = 0; s < Lz; s++) {
        const int t = dir ? (Lz - 1 - s) : s;

        H_LOAD(0);
        H_LOAD(1);
        if (s + 1 < Lz) {
            const int tn = dir ? (Lz - 2 - s) : (s + 1);
            XG_LOAD(tn, (s + 1) & 1);
        }

        const uint32_t aBase = sb + SAH + (uint32_t)((warpM * 16 + aRowOff) * RP + aColOff);
        float acc0[4] = {0.f,0.f,0.f,0.f};
        float acc1[4] = {0.f,0.f,0.f,0.f};

        asm volatile("cp.async.wait_group 2;" ::: "memory");
        __syncthreads();
#pragma unroll
        for (int ks = 0; ks < 16; ks++) {
            uint32_t a[4];
            ldsm_x4(a[0], a[1], a[2], a[3], aBase + ks * 32);
            mma16816h(acc0, a, bw[ks]);
            mma16816h(acc1, a, bw[ks] + 2);
        }
        if (s + 1 < Lz) asm volatile("cp.async.wait_group 1;" ::: "memory");
        else            asm volatile("cp.async.wait_group 0;" ::: "memory");
        __syncthreads();
#pragma unroll
        for (int ks = 16; ks < 32; ks++) {
            uint32_t a[4];
            ldsm_x4(a[0], a[1], a[2], a[3], aBase + ks * 32);
            mma16816h(acc0, a, bw[ks]);
            mma16816h(acc1, a, bw[ks] + 2);
        }

        // ---- write frags to sG ----
        {
            const int g = lane >> 2, tg = lane & 3;
            const int r = warpM * 16 + g;
            const int c = warpN * 16 + tg * 2;
            *((float2*)(sGf + r * 34 + c))           = make_float2(acc0[0], acc0[1]);
            *((float2*)(sGf + (r + 8) * 34 + c))     = make_float2(acc0[2], acc0[3]);
            *((float2*)(sGf + r * 34 + c + 8))       = make_float2(acc1[0], acc1[1]);
            *((float2*)(sGf + (r + 8) * 34 + c + 8)) = make_float2(acc1[2], acc1[3]);
        }
        __syncthreads();

        // ---- elementwise LSTM cell (fast sigmoid, exact tanh) ----
        const float* sXGf = (const float*)(dsm + SXG + (s & 1) * XGB);
#pragma unroll
        for (int r = 0; r < 2; r++) {
            const int id = tid + 256 * r;
            const int b = id >> 3, j = id & 7;
            const float iv = sGf[b*34 + j]      + sXGf[b*36 + j];
            const float fv = sGf[b*34 + 8 + j]  + sXGf[b*36 + 8 + j];
            const float gv = sGf[b*34 + 16 + j] + sXGf[b*36 + 16 + j];
            const float ov = sGf[b*34 + 24 + j] + sXGf[b*36 + 24 + j];
            const float c  = sigf(fv)*creg[r] + sigf(iv)*tanhf(gv);
            const float hv = sigf(ov)*tanhf(c);
            creg[r] = c;
            const int hcol = cb*8 + j;
            hb[b*Hz + hcol] = __float2half(hv);
            outp[(size_t)t*ts + (size_t)b*bs + dir*Hz + hcol] = hv;
        }
        grid_bar(dir, base + (++bar));
    }
#undef XG_LOAD
#undef H_LOAD
}

// ============================================================================
// Launch sequence (graph-capturable, allocation-free)
// ============================================================================
extern "C" void kernel_launch(void* const* d_in, const int* in_sizes, int n_in,
                              void* d_out, int out_size)
{
    const float* x      = (const float*)d_in[0];
    const float* Wih_f0 = (const float*)d_in[1];
    const float* Whh_f0 = (const float*)d_in[2];
    const float* bih_f0 = (const float*)d_in[3];
    const float* bhh_f0 = (const float*)d_in[4];
    const float* Wih_r0 = (const float*)d_in[5];
    const float* Whh_r0 = (const float*)d_in[6];
    const float* bih_r0 = (const float*)d_in[7];
    const float* bhh_r0 = (const float*)d_in[8];
    const float* Wih_f1 = (const float*)d_in[9];
    const float* Whh_f1 = (const float*)d_in[10];
    const float* bih_f1 = (const float*)d_in[11];
    const float* bhh_f1 = (const float*)d_in[12];
    const float* Wih_r1 = (const float*)d_in[13];
    const float* Whh_r1 = (const float*)d_in[14];
    const float* bih_r1 = (const float*)d_in[15];
    const float* bhh_r1 = (const float*)d_in[16];
    float* outp = (float*)d_out;

    cudaFuncSetAttribute(gates_gemm_mma, cudaFuncAttributeMaxDynamicSharedMemorySize, GEMM_SMEM);
    cudaFuncSetAttribute(lstm_recur_mma, cudaFuncAttributeMaxDynamicSharedMemorySize, REC_SMEM);

    const dim3 gemm_grid(Gz/128, Mz/256, 2);     // (16, 128, 2)

    // ---- layer 0 (K = 256) ----
    conv_W_f16<<<dim3((Gz*256)/1024, 2), 256>>>(Wih_f0, Wih_r0, 256);
    conv_A_f16<<<(Mz*256)/1024, 256>>>(x, 0, 8);
    gates_gemm_mma<<<gemm_grid, 256, GEMM_SMEM>>>(bih_f0, bhh_f0, bih_r0, bhh_r0, 256);
    lstm_recur_mma<<<2*NCD, 256, REC_SMEM>>>(Whh_f0, Whh_r0, outp, 0);

    // ---- layer 1 (K = 1024) ----
    conv_W_f16<<<dim3((Gz*1024)/1024, 2), 256>>>(Wih_f1, Wih_r1, 1024);
    conv_A_f16<<<(Mz*1024)/1024, 256>>>(x, 1, 10);
    gates_gemm_mma<<<gemm_grid, 256, GEMM_SMEM>>>(bih_f1, bhh_f1, bih_r1, bhh_r1, 1024);
    lstm_recur_mma<<<2*NCD, 256, REC_SMEM>>>(Whh_f1, Whh_r1, outp, 1);
}

// round 8
// speedup vs baseline: 3.9148x; 1.0306x over previous
#include <cuda_runtime.h>
#include <cuda_fp16.h>
#include <math.h>
#include <stdint.h>

// Problem constants
#define Bz 64
#define Lz 512
#define Iz 256
#define Hz 512
#define Gz 2048           // 4*H
#define Mz (Lz*Bz)        // 32768
#define NCD 64            // CTAs per direction in the recurrence kernel

// ---------------- scratch (device globals: allocation-free) ----------------
__device__ float g_xg[(size_t)2 * Mz * Gz];          // per-dir precomputed input gates (fp32)
__device__ __half g_hf[2 * Bz * Hz];                 // running h per direction (fp16)
__device__ unsigned g_cnt[2];                        // barrier arrival counters
__device__ unsigned g_gen[2];                        // barrier generation
__device__ __half g_Af [(size_t)Mz * 1024];          // fp16 activations (layer input, m = t*B+b)
__device__ __half g_Whf[(size_t)2 * Gz * 1024];      // fp16 Wih hi
__device__ __half g_Wlf[(size_t)2 * Gz * 1024];      // fp16 Wih lo

// ======================= PTX helpers (base-ISA only) =======================
__device__ __forceinline__ uint32_t smem_to_u32(const void* p) {
    uint32_t a;
    asm("{ .reg .u64 t; cvta.to.shared.u64 t, %1; cvt.u32.u64 %0, t; }" : "=r"(a) : "l"(p));
    return a;
}
__device__ __forceinline__ void cpa16(uint32_t s, const void* g) {
    asm volatile("cp.async.cg.shared.global [%0], [%1], 16;" :: "r"(s), "l"(g));
}
__device__ __forceinline__ void ldsm_x4(uint32_t& r0, uint32_t& r1, uint32_t& r2, uint32_t& r3,
                                        uint32_t a) {
    asm volatile("ldmatrix.sync.aligned.m8n8.x4.shared.b16 {%0,%1,%2,%3}, [%4];"
                 : "=r"(r0), "=r"(r1), "=r"(r2), "=r"(r3) : "r"(a));
}
__device__ __forceinline__ void mma16816h(float* d, const uint32_t* a, const uint32_t* b) {
    asm volatile("mma.sync.aligned.m16n8k16.row.col.f32.f16.f16.f32 "
                 "{%0,%1,%2,%3}, {%4,%5,%6,%7}, {%8,%9}, {%0,%1,%2,%3};"
                 : "+f"(d[0]), "+f"(d[1]), "+f"(d[2]), "+f"(d[3])
                 : "r"(a[0]), "r"(a[1]), "r"(a[2]), "r"(a[3]), "r"(b[0]), "r"(b[1]));
}
// fast sigmoid (tanh stays exact)
__device__ __forceinline__ float sigf(float x) {
    return __fdividef(1.f, 1.f + __expf(-x));
}

// ============================================================================
// Conversion kernels (layer-0 inputs only; layer-1 A is written by recurrence)
// ============================================================================
__global__ void conv_A_f16(const float* __restrict__ src)
{
    // x: [b][t][k] (K=256) -> g_Af[m= t*64+b][k]
    const size_t i = ((size_t)blockIdx.x * 256 + threadIdx.x) * 4;
    const size_t m = i >> 8;
    const size_t k = i & 255;
    const float4 v = *((const float4*)(src + ((m & 63) * 512 + (m >> 6)) * 256 + k));
    *((__half2*)(g_Af + i))     = __floats2half2_rn(v.x, v.y);
    *((__half2*)(g_Af + i + 2)) = __floats2half2_rn(v.z, v.w);
}

__global__ void conv_W_f16(const float* __restrict__ Wf, const float* __restrict__ Wr, int K)
{
    const int dir = blockIdx.y;
    const size_t i = ((size_t)blockIdx.x * 256 + threadIdx.x) * 4;   // over 2048*K
    const float* src = dir ? Wr : Wf;
    const size_t off = (size_t)dir * Gz * K;
    const float4 v = *((const float4*)(src + i));
    __half h0 = __float2half_rn(v.x), h1 = __float2half_rn(v.y);
    __half h2 = __float2half_rn(v.z), h3 = __float2half_rn(v.w);
    __half l0 = __float2half_rn(v.x - __half2float(h0));
    __half l1 = __float2half_rn(v.y - __half2float(h1));
    __half l2 = __float2half_rn(v.z - __half2float(h2));
    __half l3 = __float2half_rn(v.w - __half2float(h3));
    *((__half2*)(g_Whf + off + i))     = __halves2half2(h0, h1);
    *((__half2*)(g_Whf + off + i + 2)) = __halves2half2(h2, h3);
    *((__half2*)(g_Wlf + off + i))     = __halves2half2(l0, l1);
    *((__half2*)(g_Wlf + off + i + 2)) = __halves2half2(l2, l3);
}

// ============================================================================
// mma.sync GEMM: Xg = bias + A @ W^T.  A fp16 single; W fp16 hi+lo (2 terms).
// CTA 128x128, BK=32, 8 warps (2Mx4N), 3-stage cp.async, 2 CTAs/SM.
// smem rows padded to 80B -> conflict-free ldmatrix.
// ============================================================================
#define TAH 0
#define TBH 10240
#define TBL 20480
#define BUFB 30720
#define GEMM_SMEM (3*BUFB)

__global__ void __launch_bounds__(256, 2) gates_gemm_mma(
    const float* __restrict__ bi_f, const float* __restrict__ bh_f,
    const float* __restrict__ bi_r, const float* __restrict__ bh_r, int K)
{
    extern __shared__ char smem[];
    const uint32_t sb = smem_to_u32(smem);
    __shared__ float sBias[128];

    const int tid = threadIdx.x;
    const int wid = tid >> 5;
    const int lane = tid & 31;
    const int warpM = wid >> 2;       // 0..1
    const int warpN = wid & 3;        // 0..3
    const int dir = blockIdx.z;
    const int n0 = blockIdx.x * 128;
    const int m0 = blockIdx.y * 128;

    const __half* __restrict__ Wh = g_Whf + (size_t)dir * Gz * K;
    const __half* __restrict__ Wl = g_Wlf + (size_t)dir * Gz * K;
    const float* bi = dir ? bi_r : bi_f;
    const float* bh = dir ? bh_r : bh_f;
    if (tid < 128) sBias[tid] = bi[n0 + tid] + bh[n0 + tid];

    float acc[4][4][4];
#pragma unroll
    for (int mt = 0; mt < 4; mt++)
#pragma unroll
        for (int nt = 0; nt < 4; nt++)
#pragma unroll
            for (int q = 0; q < 4; q++) acc[mt][nt][q] = 0.f;

    const int lrow = tid >> 2;
    const int lseg = tid & 3;

#define LOAD_CHUNK(kc, boff) do { \
    _Pragma("unroll") \
    for (int i = 0; i < 2; i++) { \
        const int row = lrow + 64 * i; \
        const uint32_t so = (uint32_t)(row * 80 + lseg * 16); \
        const size_t ga = (size_t)(m0 + row) * K + (kc) + lseg * 8; \
        const size_t gb = (size_t)(n0 + row) * K + (kc) + lseg * 8; \
        cpa16(sb + (boff) + TAH + so, g_Af + ga); \
        cpa16(sb + (boff) + TBH + so, Wh + gb); \
        cpa16(sb + (boff) + TBL + so, Wl + gb); \
    } \
    asm volatile("cp.async.commit_group;" ::: "memory"); \
} while (0)

    const int nch = K >> 5;
    LOAD_CHUNK(0, 0);
    LOAD_CHUNK(32, BUFB);

    const int aRowOff = (lane & 7) + ((lane >> 3) & 1) * 8;
    const int aColOff = ((lane >> 4) & 1) * 16;
    const int bRowOff = (lane & 7) + ((lane >> 4) & 1) * 8;
    const int bColOff = ((lane >> 3) & 1) * 16;

    int buf = 0;
    for (int ch = 0; ch < nch; ch++) {
        if (ch + 1 < nch) asm volatile("cp.async.wait_group 1;" ::: "memory");
        else              asm volatile("cp.async.wait_group 0;" ::: "memory");
        __syncthreads();

        const uint32_t boff = sb + (uint32_t)(buf * BUFB);
#pragma unroll
        for (int ks = 0; ks < 2; ks++) {
            const int kb = ks * 32;
            uint32_t aH[4][4], bH[4][2], bL[4][2];
#pragma unroll
            for (int mt = 0; mt < 4; mt++) {
                const uint32_t ra = (uint32_t)((warpM * 64 + mt * 16 + aRowOff) * 80 + kb + aColOff);
                ldsm_x4(aH[mt][0], aH[mt][1], aH[mt][2], aH[mt][3], boff + TAH + ra);
            }
#pragma unroll
            for (int p = 0; p < 2; p++) {
                const uint32_t rb = (uint32_t)((warpN * 32 + p * 16 + bRowOff) * 80 + kb + bColOff);
                uint32_t r0, r1, r2, r3;
                ldsm_x4(r0, r1, r2, r3, boff + TBH + rb);
                bH[2*p][0] = r0; bH[2*p][1] = r1; bH[2*p+1][0] = r2; bH[2*p+1][1] = r3;
                ldsm_x4(r0, r1, r2, r3, boff + TBL + rb);
                bL[2*p][0] = r0; bL[2*p][1] = r1; bL[2*p+1][0] = r2; bL[2*p+1][1] = r3;
            }
#pragma unroll
            for (int mt = 0; mt < 4; mt++)
#pragma unroll
                for (int nt = 0; nt < 4; nt++) {
                    mma16816h(acc[mt][nt], aH[mt], bH[nt]);
                    mma16816h(acc[mt][nt], aH[mt], bL[nt]);
                }
        }
        if (ch + 2 < nch) {
            const int nb = (buf + 2) % 3;
            LOAD_CHUNK((ch + 2) << 5, (uint32_t)(nb * BUFB));
        }
        buf = (buf + 1) % 3;
    }

    float* __restrict__ outp = g_xg + (size_t)dir * Mz * Gz;
    const int g  = lane >> 2;
    const int tg = lane & 3;
#pragma unroll
    for (int mt = 0; mt < 4; mt++) {
        const int m = m0 + warpM * 64 + mt * 16 + g;
#pragma unroll
        for (int nt = 0; nt < 4; nt++) {
            const int nl = warpN * 32 + nt * 8 + tg * 2;
            const float b0 = sBias[nl], b1 = sBias[nl + 1];
            float2 v0 = make_float2(acc[mt][nt][0] + b0, acc[mt][nt][1] + b1);
            float2 v1 = make_float2(acc[mt][nt][2] + b0, acc[mt][nt][3] + b1);
            *((float2*)(outp + (size_t)m * Gz + n0 + nl)) = v0;
            *((float2*)(outp + (size_t)(m + 8) * Gz + n0 + nl)) = v1;
        }
    }
#undef LOAD_CHUNK
}

// ============================================================================
// Persistent recurrence v6: W-frags in registers; layer-0 writes fp16 g_Af
// directly (layer-1 A matrix); layer-1 writes fp32 dout.
// 128 CTAs (64/dir), 256 thr. CTA cb owns h-cols [cb*8,cb*8+8) -> 32 gate cols.
// ============================================================================
__device__ __forceinline__ void grid_bar(int dir, unsigned target)
{
    __syncthreads();
    if (threadIdx.x == 0) {
        __threadfence();
        const unsigned prev = atomicAdd(&g_cnt[dir], 1u);
        if (prev == (unsigned)(NCD - 1)) {
            atomicExch(&g_cnt[dir], 0u);
            __threadfence();
            atomicExch(&g_gen[dir], target);
        } else {
            while (*((volatile unsigned*)&g_gen[dir]) != target) { }
        }
        __threadfence();
    }
    __syncthreads();
}

// dynamic smem layout (bytes)
#define RP 1040                   // row pitch: 520 halfs (512 + 8 pad)
#define SWH  0                    // [32][520] fp16   33280 B (init staging only)
#define SAH  33280                // [64][520] fp16   66560 B
#define SXG  99840                // 2 x [64][36] fp32  18432 B
#define XGB  9216                 // xg buffer stride
#define SGT  118272               // [64][34] fp32     8704 B
#define REC_SMEM 126976

__global__ void __launch_bounds__(256) lstm_recur_mma(
    const float* __restrict__ Whh_f, const float* __restrict__ Whh_r,
    float* __restrict__ dout, int layer)
{
    extern __shared__ char dsm[];
    const uint32_t sb = smem_to_u32(dsm);
    __shared__ unsigned s_base;

    const int dir = (int)(blockIdx.x) / NCD;
    const int cb  = (int)(blockIdx.x) % NCD;
    const float* __restrict__ W  = dir ? Whh_r : Whh_f;
    const float* __restrict__ xg = g_xg + (size_t)dir * Mz * Gz;
    __half* hb = g_hf + dir * Bz * Hz;

    const int tid = threadIdx.x;
    const int wid = tid >> 5;
    const int lane = tid & 31;
    const int warpM = wid & 3;        // 4 warps over M=64 (16 rows each)
    const int warpN = wid >> 2;       // 2 warps over N=32 (16 cols each)

    if (tid == 0) s_base = *((volatile unsigned*)&g_gen[dir]);

    // ---- stage Whh slice -> fp16 smem (one time), then lift to registers ----
    __half* sW = (__half*)(dsm + SWH);
#pragma unroll
    for (int i = 0; i < 16; i++) {
        const int idx = tid + 256 * i;       // 0..4095 over 32 rows x 128 float4
        const int n  = idx >> 7;             // local gate col 0..31
        const int f4 = idx & 127;
        const int gcol = (n >> 3) * Hz + cb * 8 + (n & 7);
        const float4 v = *((const float4*)(W + (size_t)gcol * Hz + f4 * 4));
        __half* ph = sW + n * 520 + f4 * 4;
        ph[0] = __float2half_rn(v.x); ph[1] = __float2half_rn(v.y);
        ph[2] = __float2half_rn(v.z); ph[3] = __float2half_rn(v.w);
    }

    // zero-init owned h columns (fp16)
#pragma unroll
    for (int r = 0; r < 2; r++) {
        const int id = tid + 256 * r;
        hb[(id >> 3) * Hz + cb * 8 + (id & 7)] = __float2half(0.f);
    }
    __syncthreads();

    const int aRowOff = (lane & 7) + ((lane >> 3) & 1) * 8;
    const int aColOff = ((lane >> 4) & 1) * 16;
    const int bRowOff = (lane & 7) + ((lane >> 4) & 1) * 8;
    const int bColOff = ((lane >> 3) & 1) * 16;

    // W fragments -> registers (step-invariant): 32 ks x 4 regs
    uint32_t bw[32][4];
    {
        const uint32_t bBase = sb + SWH + (uint32_t)((warpN * 16 + bRowOff) * RP + bColOff);
#pragma unroll
        for (int ks = 0; ks < 32; ks++)
            ldsm_x4(bw[ks][0], bw[ks][1], bw[ks][2], bw[ks][3], bBase + ks * 32);
    }

    const unsigned base = s_base;
    unsigned bar = 0;
    float creg[2] = {0.f, 0.f};
    grid_bar(dir, base + (++bar));   // h=0 visible everywhere

    float* sGf = (float*)(dsm + SGT);   // [64][34]

#define XG_LOAD(t_, buf_) do { \
    _Pragma("unroll") \
    for (int i = 0; i < 2; i++) { \
        const int idx = tid + 256 * i; \
        const int b = idx >> 3, rem = idx & 7; \
        const int g = rem >> 1, q = rem & 1; \
        cpa16(sb + SXG + (buf_) * XGB + b * 144 + g * 32 + q * 16, \
              xg + ((size_t)(t_) * Bz + b) * Gz + g * Hz + cb * 8 + q * 4); \
    } \
    asm volatile("cp.async.commit_group;" ::: "memory"); \
} while (0)
#define H_LOAD(c0_) do { \
    _Pragma("unroll") \
    for (int i = 0; i < 8; i++) { \
        const int idx = tid + 256 * i;   /* 0..2047 */ \
        const int b = idx >> 5, seg = (idx & 31) + (c0_) * 32; \
        cpa16(sb + SAH + b * RP + seg * 16, hb + b * Hz + seg * 8); \
    } \
    asm volatile("cp.async.commit_group;" ::: "memory"); \
} while (0)

    // prologue: xg for step 0 into buffer 0
    {
        const int t0 = dir ? (Lz - 1) : 0;
        XG_LOAD(t0, 0);
    }

    for (int s = 0; s < Lz; s++) {
        const int t = dir ? (Lz - 1 - s) : s;

        H_LOAD(0);
        H_LOAD(1);
        if (s + 1 < Lz) {
            const int tn = dir ? (Lz - 2 - s) : (s + 1);
            XG_LOAD(tn, (s + 1) & 1);
        }

        const uint32_t aBase = sb + SAH + (uint32_t)((warpM * 16 + aRowOff) * RP + aColOff);
        float acc0[4] = {0.f,0.f,0.f,0.f};
        float acc1[4] = {0.f,0.f,0.f,0.f};

        asm volatile("cp.async.wait_group 2;" ::: "memory");
        __syncthreads();
#pragma unroll
        for (int ks = 0; ks < 16; ks++) {
            uint32_t a[4];
            ldsm_x4(a[0], a[1], a[2], a[3], aBase + ks * 32);
            mma16816h(acc0, a, bw[ks]);
            mma16816h(acc1, a, bw[ks] + 2);
        }
        if (s + 1 < Lz) asm volatile("cp.async.wait_group 1;" ::: "memory");
        else            asm volatile("cp.async.wait_group 0;" ::: "memory");
        __syncthreads();
#pragma unroll
        for (int ks = 16; ks < 32; ks++) {
            uint32_t a[4];
            ldsm_x4(a[0], a[1], a[2], a[3], aBase + ks * 32);
            mma16816h(acc0, a, bw[ks]);
            mma16816h(acc1, a, bw[ks] + 2);
        }

        // ---- write frags to sG ----
        {
            const int g = lane >> 2, tg = lane & 3;
            const int r = warpM * 16 + g;
            const int c = warpN * 16 + tg * 2;
            *((float2*)(sGf + r * 34 + c))           = make_float2(acc0[0], acc0[1]);
            *((float2*)(sGf + (r + 8) * 34 + c))     = make_float2(acc0[2], acc0[3]);
            *((float2*)(sGf + r * 34 + c + 8))       = make_float2(acc1[0], acc1[1]);
            *((float2*)(sGf + (r + 8) * 34 + c + 8)) = make_float2(acc1[2], acc1[3]);
        }
        __syncthreads();

        // ---- elementwise LSTM cell (fast sigmoid, exact tanh) ----
        const float* sXGf = (const float*)(dsm + SXG + (s & 1) * XGB);
#pragma unroll
        for (int r = 0; r < 2; r++) {
            const int id = tid + 256 * r;
            const int b = id >> 3, j = id & 7;
            const float iv = sGf[b*34 + j]      + sXGf[b*36 + j];
            const float fv = sGf[b*34 + 8 + j]  + sXGf[b*36 + 8 + j];
            const float gv = sGf[b*34 + 16 + j] + sXGf[b*36 + 16 + j];
            const float ov = sGf[b*34 + 24 + j] + sXGf[b*36 + 24 + j];
            const float c  = sigf(fv)*creg[r] + sigf(iv)*tanhf(gv);
            const float hv = sigf(ov)*tanhf(c);
            creg[r] = c;
            const int hcol = cb*8 + j;
            const __half hvh = __float2half(hv);
            hb[b*Hz + hcol] = hvh;
            if (layer) {
                dout[(size_t)b*(Lz*2*Hz) + (size_t)t*(2*Hz) + dir*Hz + hcol] = hv;
            } else {
                g_Af[((size_t)t*Bz + b)*1024 + dir*Hz + hcol] = hvh;
            }
        }
        grid_bar(dir, base + (++bar));
    }
#undef XG_LOAD
#undef H_LOAD
}

// ============================================================================
// Launch sequence (graph-capturable, allocation-free)
// ============================================================================
extern "C" void kernel_launch(void* const* d_in, const int* in_sizes, int n_in,
                              void* d_out, int out_size)
{
    const float* x      = (const float*)d_in[0];
    const float* Wih_f0 = (const float*)d_in[1];
    const float* Whh_f0 = (const float*)d_in[2];
    const float* bih_f0 = (const float*)d_in[3];
    const float* bhh_f0 = (const float*)d_in[4];
    const float* Wih_r0 = (const float*)d_in[5];
    const float* Whh_r0 = (const float*)d_in[6];
    const float* bih_r0 = (const float*)d_in[7];
    const float* bhh_r0 = (const float*)d_in[8];
    const float* Wih_f1 = (const float*)d_in[9];
    const float* Whh_f1 = (const float*)d_in[10];
    const float* bih_f1 = (const float*)d_in[11];
    const float* bhh_f1 = (const float*)d_in[12];
    const float* Wih_r1 = (const float*)d_in[13];
    const float* Whh_r1 = (const float*)d_in[14];
    const float* bih_r1 = (const float*)d_in[15];
    const float* bhh_r1 = (const float*)d_in[16];
    float* outp = (float*)d_out;

    cudaFuncSetAttribute(gates_gemm_mma, cudaFuncAttributeMaxDynamicSharedMemorySize, GEMM_SMEM);
    cudaFuncSetAttribute(lstm_recur_mma, cudaFuncAttributeMaxDynamicSharedMemorySize, REC_SMEM);

    const dim3 gemm_grid(Gz/128, Mz/128, 2);     // (16, 256, 2)

    // ---- layer 0 (K = 256) ----
    conv_W_f16<<<dim3((Gz*256)/1024, 2), 256>>>(Wih_f0, Wih_r0, 256);
    conv_A_f16<<<(Mz*256)/1024, 256>>>(x);
    gates_gemm_mma<<<gemm_grid, 256, GEMM_SMEM>>>(bih_f0, bhh_f0, bih_r0, bhh_r0, 256);
    lstm_recur_mma<<<2*NCD, 256, REC_SMEM>>>(Whh_f0, Whh_r0, outp, 0);

    // ---- layer 1 (K = 1024; A written by layer-0 recurrence) ----
    conv_W_f16<<<dim3((Gz*1024)/1024, 2), 256>>>(Wih_f1, Wih_r1, 1024);
    gates_gemm_mma<<<gemm_grid, 256, GEMM_SMEM>>>(bih_f1, bhh_f1, bih_r1, bhh_r1, 1024);
    lstm_recur_mma<<<2*NCD, 256, REC_SMEM>>>(Whh_f1, Whh_r1, outp, 1);
}

// round 10
// speedup vs baseline: 4.2160x; 1.0769x over previous
#include <cuda_runtime.h>
#include <cuda_fp16.h>
#include <math.h>
#include <stdint.h>

// Problem constants
#define Bz 64
#define Lz 512
#define Iz 256
#define Hz 512
#define Gz 2048           // 4*H
#define Mz (Lz*Bz)        // 32768
#define NCD 64            // CTAs per direction in the recurrence kernel

// ---------------- scratch (device globals: allocation-free) ----------------
__device__ float g_xg[(size_t)2 * Mz * Gz];          // per-dir precomputed input gates (fp32)
__device__ __half g_hf[2 * Bz * Hz];                 // running h per direction (fp16)
__device__ unsigned g_cnt[2];                        // barrier arrival counters
__device__ unsigned g_gen[2];                        // barrier generation
__device__ __half g_Af [(size_t)Mz * 1024];          // fp16 activations (layer input, m = t*B+b)
__device__ __half g_Whf[(size_t)2 * Gz * 1024];      // fp16 Wih hi
__device__ __half g_Wlf[(size_t)2 * Gz * 1024];      // fp16 Wih lo

// ======================= PTX helpers (base-ISA only) =======================
__device__ __forceinline__ uint32_t smem_to_u32(const void* p) {
    uint32_t a;
    asm("{ .reg .u64 t; cvta.to.shared.u64 t, %1; cvt.u32.u64 %0, t; }" : "=r"(a) : "l"(p));
    return a;
}
__device__ __forceinline__ void cpa16(uint32_t s, const void* g) {
    asm volatile("cp.async.cg.shared.global [%0], [%1], 16;" :: "r"(s), "l"(g));
}
__device__ __forceinline__ void ldsm_x4(uint32_t& r0, uint32_t& r1, uint32_t& r2, uint32_t& r3,
                                        uint32_t a) {
    asm volatile("ldmatrix.sync.aligned.m8n8.x4.shared.b16 {%0,%1,%2,%3}, [%4];"
                 : "=r"(r0), "=r"(r1), "=r"(r2), "=r"(r3) : "r"(a));
}
__device__ __forceinline__ void mma16816h(float* d, const uint32_t* a, const uint32_t* b) {
    asm volatile("mma.sync.aligned.m16n8k16.row.col.f32.f16.f16.f32 "
                 "{%0,%1,%2,%3}, {%4,%5,%6,%7}, {%8,%9}, {%0,%1,%2,%3};"
                 : "+f"(d[0]), "+f"(d[1]), "+f"(d[2]), "+f"(d[3])
                 : "r"(a[0]), "r"(a[1]), "r"(a[2]), "r"(a[3]), "r"(b[0]), "r"(b[1]));
}
// fast sigmoid (tanh stays exact)
__device__ __forceinline__ float sigf(float x) {
    return __fdividef(1.f, 1.f + __expf(-x));
}

// ============================================================================
// Conversion kernels (layer-0 inputs only; layer-1 A is written by recurrence)
// ============================================================================
__global__ void conv_A_f16(const float* __restrict__ src)
{
    // x: [b][t][k] (K=256) -> g_Af[m= t*64+b][k]
    const size_t i = ((size_t)blockIdx.x * 256 + threadIdx.x) * 4;
    const size_t m = i >> 8;
    const size_t k = i & 255;
    const float4 v = *((const float4*)(src + ((m & 63) * 512 + (m >> 6)) * 256 + k));
    *((__half2*)(g_Af + i))     = __floats2half2_rn(v.x, v.y);
    *((__half2*)(g_Af + i + 2)) = __floats2half2_rn(v.z, v.w);
}

__global__ void conv_W_f16(const float* __restrict__ Wf, const float* __restrict__ Wr, int K)
{
    const int dir = blockIdx.y;
    const size_t i = ((size_t)blockIdx.x * 256 + threadIdx.x) * 4;   // over 2048*K
    const float* src = dir ? Wr : Wf;
    const size_t off = (size_t)dir * Gz * K;
    const float4 v = *((const float4*)(src + i));
    __half h0 = __float2half_rn(v.x), h1 = __float2half_rn(v.y);
    __half h2 = __float2half_rn(v.z), h3 = __float2half_rn(v.w);
    __half l0 = __float2half_rn(v.x - __half2float(h0));
    __half l1 = __float2half_rn(v.y - __half2float(h1));
    __half l2 = __float2half_rn(v.z - __half2float(h2));
    __half l3 = __float2half_rn(v.w - __half2float(h3));
    *((__half2*)(g_Whf + off + i))     = __halves2half2(h0, h1);
    *((__half2*)(g_Whf + off + i + 2)) = __halves2half2(h2, h3);
    *((__half2*)(g_Wlf + off + i))     = __halves2half2(l0, l1);
    *((__half2*)(g_Wlf + off + i + 2)) = __halves2half2(l2, l3);
}

// ============================================================================
// mma.sync GEMM: Xg = bias + A @ W^T.  A fp16 single; W fp16 hi (+lo if terms=2).
// CTA 128x128, BK=32, 8 warps (2Mx4N), 3-stage cp.async, 2 CTAs/SM.
// smem rows padded to 80B -> conflict-free ldmatrix.
// ============================================================================
#define TAH 0
#define TBH 10240
#define TBL 20480
#define BUFB 30720
#define GEMM_SMEM (3*BUFB)

__global__ void __launch_bounds__(256, 2) gates_gemm_mma(
    const float* __restrict__ bi_f, const float* __restrict__ bh_f,
    const float* __restrict__ bi_r, const float* __restrict__ bh_r, int K, int terms)
{
    extern __shared__ char smem[];
    const uint32_t sb = smem_to_u32(smem);
    __shared__ float sBias[128];

    const int tid = threadIdx.x;
    const int wid = tid >> 5;
    const int lane = tid & 31;
    const int warpM = wid >> 2;       // 0..1
    const int warpN = wid & 3;        // 0..3
    const int dir = blockIdx.z;
    const int n0 = blockIdx.x * 128;
    const int m0 = blockIdx.y * 128;

    const __half* __restrict__ Wh = g_Whf + (size_t)dir * Gz * K;
    const __half* __restrict__ Wl = g_Wlf + (size_t)dir * Gz * K;
    const float* bi = dir ? bi_r : bi_f;
    const float* bh = dir ? bh_r : bh_f;
    if (tid < 128) sBias[tid] = bi[n0 + tid] + bh[n0 + tid];

    float acc[4][4][4];
#pragma unroll
    for (int mt = 0; mt < 4; mt++)
#pragma unroll
        for (int nt = 0; nt < 4; nt++)
#pragma unroll
            for (int q = 0; q < 4; q++) acc[mt][nt][q] = 0.f;

    const int lrow = tid >> 2;
    const int lseg = tid & 3;

#define LOAD_CHUNK(kc, boff) do { \
    _Pragma("unroll") \
    for (int i = 0; i < 2; i++) { \
        const int row = lrow + 64 * i; \
        const uint32_t so = (uint32_t)(row * 80 + lseg * 16); \
        const size_t ga = (size_t)(m0 + row) * K + (kc) + lseg * 8; \
        const size_t gb = (size_t)(n0 + row) * K + (kc) + lseg * 8; \
        cpa16(sb + (boff) + TAH + so, g_Af + ga); \
        cpa16(sb + (boff) + TBH + so, Wh + gb); \
        if (terms == 2) cpa16(sb + (boff) + TBL + so, Wl + gb); \
    } \
    asm volatile("cp.async.commit_group;" ::: "memory"); \
} while (0)

    const int nch = K >> 5;
    LOAD_CHUNK(0, 0);
    LOAD_CHUNK(32, BUFB);

    const int aRowOff = (lane & 7) + ((lane >> 3) & 1) * 8;
    const int aColOff = ((lane >> 4) & 1) * 16;
    const int bRowOff = (lane & 7) + ((lane >> 4) & 1) * 8;
    const int bColOff = ((lane >> 3) & 1) * 16;

    int buf = 0;
    for (int ch = 0; ch < nch; ch++) {
        if (ch + 1 < nch) asm volatile("cp.async.wait_group 1;" ::: "memory");
        else              asm volatile("cp.async.wait_group 0;" ::: "memory");
        __syncthreads();

        const uint32_t boff = sb + (uint32_t)(buf * BUFB);
#pragma unroll
        for (int ks = 0; ks < 2; ks++) {
            const int kb = ks * 32;
            uint32_t aH[4][4], bH[4][2];
#pragma unroll
            for (int mt = 0; mt < 4; mt++) {
                const uint32_t ra = (uint32_t)((warpM * 64 + mt * 16 + aRowOff) * 80 + kb + aColOff);
                ldsm_x4(aH[mt][0], aH[mt][1], aH[mt][2], aH[mt][3], boff + TAH + ra);
            }
#pragma unroll
            for (int p = 0; p < 2; p++) {
                const uint32_t rb = (uint32_t)((warpN * 32 + p * 16 + bRowOff) * 80 + kb + bColOff);
                uint32_t r0, r1, r2, r3;
                ldsm_x4(r0, r1, r2, r3, boff + TBH + rb);
                bH[2*p][0] = r0; bH[2*p][1] = r1; bH[2*p+1][0] = r2; bH[2*p+1][1] = r3;
            }
#pragma unroll
            for (int mt = 0; mt < 4; mt++)
#pragma unroll
                for (int nt = 0; nt < 4; nt++)
                    mma16816h(acc[mt][nt], aH[mt], bH[nt]);
            if (terms == 2) {
                uint32_t bL[4][2];
#pragma unroll
                for (int p = 0; p < 2; p++) {
                    const uint32_t rb = (uint32_t)((warpN * 32 + p * 16 + bRowOff) * 80 + kb + bColOff);
                    uint32_t r0, r1, r2, r3;
                    ldsm_x4(r0, r1, r2, r3, boff + TBL + rb);
                    bL[2*p][0] = r0; bL[2*p][1] = r1; bL[2*p+1][0] = r2; bL[2*p+1][1] = r3;
                }
#pragma unroll
                for (int mt = 0; mt < 4; mt++)
#pragma unroll
                    for (int nt = 0; nt < 4; nt++)
                        mma16816h(acc[mt][nt], aH[mt], bL[nt]);
            }
        }
        if (ch + 2 < nch) {
            const int nb = (buf + 2) % 3;
            LOAD_CHUNK((ch + 2) << 5, (uint32_t)(nb * BUFB));
        }
        buf = (buf + 1) % 3;
    }

    float* __restrict__ outp = g_xg + (size_t)dir * Mz * Gz;
    const int g  = lane >> 2;
    const int tg = lane & 3;
#pragma unroll
    for (int mt = 0; mt < 4; mt++) {
        const int m = m0 + warpM * 64 + mt * 16 + g;
#pragma unroll
        for (int nt = 0; nt < 4; nt++) {
            const int nl = warpN * 32 + nt * 8 + tg * 2;
            const float b0 = sBias[nl], b1 = sBias[nl + 1];
            float2 v0 = make_float2(acc[mt][nt][0] + b0, acc[mt][nt][1] + b1);
            float2 v1 = make_float2(acc[mt][nt][2] + b0, acc[mt][nt][3] + b1);
            *((float2*)(outp + (size_t)m * Gz + n0 + nl)) = v0;
            *((float2*)(outp + (size_t)(m + 8) * Gz + n0 + nl)) = v1;
        }
    }
#undef LOAD_CHUNK
}

// ============================================================================
// Persistent recurrence (R8-proven): atomic grid barrier; W-frags in registers;
// layer-0 writes fp16 g_Af directly (layer-1 A matrix); layer-1 writes dout.
// 128 CTAs (64/dir), 256 thr. CTA cb owns h-cols [cb*8,cb*8+8) -> 32 gate cols.
// ============================================================================
__device__ __forceinline__ void grid_bar(int dir, unsigned target)
{
    __syncthreads();
    if (threadIdx.x == 0) {
        __threadfence();
        const unsigned prev = atomicAdd(&g_cnt[dir], 1u);
        if (prev == (unsigned)(NCD - 1)) {
            atomicExch(&g_cnt[dir], 0u);
            __threadfence();
            atomicExch(&g_gen[dir], target);
        } else {
            while (*((volatile unsigned*)&g_gen[dir]) != target) { }
        }
        __threadfence();
    }
    __syncthreads();
}

// dynamic smem layout (bytes)
#define RP 1040                   // row pitch: 520 halfs (512 + 8 pad)
#define SWH  0                    // [32][520] fp16   33280 B (init staging only)
#define SAH  33280                // [64][520] fp16   66560 B
#define SXG  99840                // 2 x [64][36] fp32  18432 B
#define XGB  9216                 // xg buffer stride
#define SGT  118272               // [64][34] fp32     8704 B
#define REC_SMEM 126976

__global__ void __launch_bounds__(256) lstm_recur_mma(
    const float* __restrict__ Whh_f, const float* __restrict__ Whh_r,
    float* __restrict__ dout, int layer)
{
    extern __shared__ char dsm[];
    const uint32_t sb = smem_to_u32(dsm);
    __shared__ unsigned s_base;

    const int dir = (int)(blockIdx.x) / NCD;
    const int cb  = (int)(blockIdx.x) % NCD;
    const float* __restrict__ W  = dir ? Whh_r : Whh_f;
    const float* __restrict__ xg = g_xg + (size_t)dir * Mz * Gz;
    __half* hb = g_hf + dir * Bz * Hz;

    const int tid = threadIdx.x;
    const int wid = tid >> 5;
    const int lane = tid & 31;
    const int warpM = wid & 3;        // 4 warps over M=64 (16 rows each)
    const int warpN = wid >> 2;       // 2 warps over N=32 (16 cols each)

    if (tid == 0) s_base = *((volatile unsigned*)&g_gen[dir]);

    // ---- stage Whh slice -> fp16 smem (one time), then lift to registers ----
    __half* sW = (__half*)(dsm + SWH);
#pragma unroll
    for (int i = 0; i < 16; i++) {
        const int idx = tid + 256 * i;       // 0..4095 over 32 rows x 128 float4
        const int n  = idx >> 7;             // local gate col 0..31
        const int f4 = idx & 127;
        const int gcol = (n >> 3) * Hz + cb * 8 + (n & 7);
        const float4 v = *((const float4*)(W + (size_t)gcol * Hz + f4 * 4));
        __half* ph = sW + n * 520 + f4 * 4;
        ph[0] = __float2half_rn(v.x); ph[1] = __float2half_rn(v.y);
        ph[2] = __float2half_rn(v.z); ph[3] = __float2half_rn(v.w);
    }

    // zero-init owned h columns (fp16)
#pragma unroll
    for (int r = 0; r < 2; r++) {
        const int id = tid + 256 * r;
        hb[(id >> 3) * Hz + cb * 8 + (id & 7)] = __float2half(0.f);
    }
    __syncthreads();

    const int aRowOff = (lane & 7) + ((lane >> 3) & 1) * 8;
    const int aColOff = ((lane >> 4) & 1) * 16;
    const int bRowOff = (lane & 7) + ((lane >> 4) & 1) * 8;
    const int bColOff = ((lane >> 3) & 1) * 16;

    // W fragments -> registers (step-invariant): 32 ks x 4 regs
    uint32_t bw[32][4];
    {
        const uint32_t bBase = sb + SWH + (uint32_t)((warpN * 16 + bRowOff) * RP + bColOff);
#pragma unroll
        for (int ks = 0; ks < 32; ks++)
            ldsm_x4(bw[ks][0], bw[ks][1], bw[ks][2], bw[ks][3], bBase + ks * 32);
    }

    const unsigned base = s_base;
    unsigned bar = 0;
    float creg[2] = {0.f, 0.f};
    grid_bar(dir, base + (++bar));   // h=0 visible everywhere

    float* sGf = (float*)(dsm + SGT);   // [64][34]

#define XG_LOAD(t_, buf_) do { \
    _Pragma("unroll") \
    for (int i = 0; i < 2; i++) { \
        const int idx = tid + 256 * i; \
        const int b = idx >> 3, rem = idx & 7; \
        const int g = rem >> 1, q = rem & 1; \
        cpa16(sb + SXG + (buf_) * XGB + b * 144 + g * 32 + q * 16, \
              xg + ((size_t)(t_) * Bz + b) * Gz + g * Hz + cb * 8 + q * 4); \
    } \
    asm volatile("cp.async.commit_group;" ::: "memory"); \
} while (0)
#define H_LOAD(c0_) do { \
    _Pragma("unroll") \
    for (int i = 0; i < 8; i++) { \
        const int idx = tid + 256 * i;   /* 0..2047 */ \
        const int b = idx >> 5, seg = (idx & 31) + (c0_) * 32; \
        cpa16(sb + SAH + b * RP + seg * 16, hb + b * Hz + seg * 8); \
    } \
    asm volatile("cp.async.commit_group;" ::: "memory"); \
} while (0)

    // prologue: xg for step 0 into buffer 0
    {
        const int t0 = dir ? (Lz - 1) : 0;
        XG_LOAD(t0, 0);
    }

    for (int s = 0; s < Lz; s++) {
        const int t = dir ? (Lz - 1 - s) : s;

        H_LOAD(0);
        H_LOAD(1);
        if (s + 1 < Lz) {
            const int tn = dir ? (Lz - 2 - s) : (s + 1);
            XG_LOAD(tn, (s + 1) & 1);
        }

        const uint32_t aBase = sb + SAH + (uint32_t)((warpM * 16 + aRowOff) * RP + aColOff);
        float acc0[4] = {0.f,0.f,0.f,0.f};
        float acc1[4] = {0.f,0.f,0.f,0.f};

        asm volatile("cp.async.wait_group 2;" ::: "memory");
        __syncthreads();
#pragma unroll
        for (int ks = 0; ks < 16; ks++) {
            uint32_t a[4];
            ldsm_x4(a[0], a[1], a[2], a[3], aBase + ks * 32);
            mma16816h(acc0, a, bw[ks]);
            mma16816h(acc1, a, bw[ks] + 2);
        }
        if (s + 1 < Lz) asm volatile("cp.async.wait_group 1;" ::: "memory");
        else            asm volatile("cp.async.wait_group 0;" ::: "memory");
        __syncthreads();
#pragma unroll
        for (int ks = 16; ks < 32; ks++) {
            uint32_t a[4];
            ldsm_x4(a[0], a[1], a[2], a[3], aBase + ks * 32);
            mma16816h(acc0, a, bw[ks]);
            mma16816h(acc1, a, bw[ks] + 2);
        }

        // ---- write frags to sG ----
        {
            const int g = lane >> 2, tg = lane & 3;
            const int r = warpM * 16 + g;
            const int c = warpN * 16 + tg * 2;
            *((float2*)(sGf + r * 34 + c))           = make_float2(acc0[0], acc0[1]);
            *((float2*)(sGf + (r + 8) * 34 + c))     = make_float2(acc0[2], acc0[3]);
            *((float2*)(sGf + r * 34 + c + 8))       = make_float2(acc1[0], acc1[1]);
            *((float2*)(sGf + (r + 8) * 34 + c + 8)) = make_float2(acc1[2], acc1[3]);
        }
        __syncthreads();

        // ---- elementwise LSTM cell (fast sigmoid, exact tanh) ----
        const float* sXGf = (const float*)(dsm + SXG + (s & 1) * XGB);
#pragma unroll
        for (int r = 0; r < 2; r++) {
            const int id = tid + 256 * r;
            const int b = id >> 3, j = id & 7;
            const float iv = sGf[b*34 + j]      + sXGf[b*36 + j];
            const float fv = sGf[b*34 + 8 + j]  + sXGf[b*36 + 8 + j];
            const float gv = sGf[b*34 + 16 + j] + sXGf[b*36 + 16 + j];
            const float ov = sGf[b*34 + 24 + j] + sXGf[b*36 + 24 + j];
            const float c  = sigf(fv)*creg[r] + sigf(iv)*tanhf(gv);
            const float hv = sigf(ov)*tanhf(c);
            creg[r] = c;
            const int hcol = cb*8 + j;
            const __half hvh = __float2half(hv);
            hb[b*Hz + hcol] = hvh;
            if (layer) {
                dout[(size_t)b*(Lz*2*Hz) + (size_t)t*(2*Hz) + dir*Hz + hcol] = hv;
            } else {
                g_Af[((size_t)t*Bz + b)*1024 + dir*Hz + hcol] = hvh;
            }
        }
        grid_bar(dir, base + (++bar));
    }
#undef XG_LOAD
#undef H_LOAD
}

// ============================================================================
// Launch sequence (graph-capturable, allocation-free)
// ============================================================================
extern "C" void kernel_launch(void* const* d_in, const int* in_sizes, int n_in,
                              void* d_out, int out_size)
{
    const float* x      = (const float*)d_in[0];
    const float* Wih_f0 = (const float*)d_in[1];
    const float* Whh_f0 = (const float*)d_in[2];
    const float* bih_f0 = (const float*)d_in[3];
    const float* bhh_f0 = (const float*)d_in[4];
    const float* Wih_r0 = (const float*)d_in[5];
    const float* Whh_r0 = (const float*)d_in[6];
    const float* bih_r0 = (const float*)d_in[7];
    const float* bhh_r0 = (const float*)d_in[8];
    const float* Wih_f1 = (const float*)d_in[9];
    const float* Whh_f1 = (const float*)d_in[10];
    const float* bih_f1 = (const float*)d_in[11];
    const float* bhh_f1 = (const float*)d_in[12];
    const float* Wih_r1 = (const float*)d_in[13];
    const float* Whh_r1 = (const float*)d_in[14];
    const float* bih_r1 = (const float*)d_in[15];
    const float* bhh_r1 = (const float*)d_in[16];
    float* outp = (float*)d_out;

    cudaFuncSetAttribute(gates_gemm_mma, cudaFuncAttributeMaxDynamicSharedMemorySize, GEMM_SMEM);
    cudaFuncSetAttribute(lstm_recur_mma, cudaFuncAttributeMaxDynamicSharedMemorySize, REC_SMEM);

    const dim3 gemm_grid(Gz/128, Mz/128, 2);     // (16, 256, 2)

    // ---- layer 0 (K = 256, 2-term W) ----
    conv_W_f16<<<dim3((Gz*256)/1024, 2), 256>>>(Wih_f0, Wih_r0, 256);
    conv_A_f16<<<(Mz*256)/1024, 256>>>(x);
    gates_gemm_mma<<<gemm_grid, 256, GEMM_SMEM>>>(bih_f0, bhh_f0, bih_r0, bhh_r0, 256, 2);
    lstm_recur_mma<<<2*NCD, 256, REC_SMEM>>>(Whh_f0, Whh_r0, outp, 0);

    // ---- layer 1 (K = 1024, 1-term W; A written by layer-0 recurrence) ----
    conv_W_f16<<<dim3((Gz*1024)/1024, 2), 256>>>(Wih_f1, Wih_r1, 1024);
    gates_gemm_mma<<<gemm_grid, 256, GEMM_SMEM>>>(bih_f1, bhh_f1, bih_r1, bhh_r1, 1024, 1);
    lstm_recur_mma<<<2*NCD, 256, REC_SMEM>>>(Whh_f1, Whh_r1, outp, 1);
}